// round 11
// baseline (speedup 1.0000x reference)
#include <cuda_runtime.h>
#include <math.h>
#include <stdint.h>

typedef unsigned int u32;

// ---------------------------------------------------------------------------
// Problem constants
// ---------------------------------------------------------------------------
constexpr int B_    = 16;
constexpr int C_    = 256;
constexpr int L_    = 2048;
constexpr int ZD_   = 128;
constexpr int TEMB_ = 512;
constexpr size_t BCL = (size_t)B_ * C_ * L_;
constexpr size_t BLL = (size_t)B_ * L_ * L_;

// ---------------------------------------------------------------------------
// Scratch (device globals; allocation-free per harness rules)
// ---------------------------------------------------------------------------
__device__ float  g_t1 [BCL];                    // silu(norm(.)) staging (tf32)
__device__ float  g_h  [BCL];                    // conv1 output
__device__ float  g_x1 [BCL];                    // x + conv2(...)
__device__ float  g_hnT[BCL];                    // norm(x1)^T [B][L][C] (tf32)
__device__ float  g_qk [(size_t)B_ * L_ * 512];  // q|k fused: [B][L][512] (tf32)
__device__ float  g_v  [BCL];                    // v   [B][C][L] (tf32)
__device__ float  g_h2T[BCL];                    // attn out [B][L][C] (tf32)
__device__ float  g_sc [BLL];                    // scores fp32 / softmax out (tf32)
__device__ float  g_add[B_ * C_];                // temb/z projection vector
__device__ float2 g_st [B_ * C_];                // per-row norm fold (fA, fB)
// tf32-pre-rounded weights: qk(512x256) | vw | pw | c1w | c2w ; then qk bias
__device__ float g_wr[512 * C_ + 2 * C_ * C_ + 2 * C_ * C_ * 3 + 512];

static __device__ __forceinline__ float silu_f(float x) {
    return x / (1.f + expf(-x));
}

static __device__ __forceinline__ float f2tf_f(float x) {
    u32 r;
    asm("cvt.rna.tf32.f32 %0, %1;" : "=r"(r) : "f"(x));
    return __uint_as_float(r);
}

#define MMA_TF32(d, a, b)                                                     \
    asm volatile("mma.sync.aligned.m16n8k8.row.col.f32.tf32.tf32.f32 "       \
                 "{%0,%1,%2,%3},{%4,%5,%6,%7},{%8,%9},{%0,%1,%2,%3};"         \
                 : "+f"(d[0]), "+f"(d[1]), "+f"(d[2]), "+f"(d[3])             \
                 : "r"(a[0]), "r"(a[1]), "r"(a[2]), "r"(a[3]),                \
                   "r"(b[0]), "r"(b[1]))

#define CP_ASYNC16(dst_u32, src_ptr)                                          \
    asm volatile("cp.async.cg.shared.global [%0], [%1], 16;"                  \
                 :: "r"(dst_u32), "l"(src_ptr))
#define CP_COMMIT()  asm volatile("cp.async.commit_group;")
#define CP_WAIT0()   asm volatile("cp.async.wait_group 0;")
#define CP_WAIT1()   asm volatile("cp.async.wait_group 1;")
#define CP_WAIT2()   asm volatile("cp.async.wait_group 2;")

static __device__ __forceinline__ u32 smem_u32(const void* p) {
    return (u32)__cvta_generic_to_shared(p);
}

// ---------------------------------------------------------------------------
// Weight prep kernels (tiny, run once per launch)
// ---------------------------------------------------------------------------
__global__ void round_tf32_kernel(const float* __restrict__ in,
                                  float* __restrict__ out, int n)
{
    int i = blockIdx.x * 256 + threadIdx.x;
    if (i < n) out[i] = f2tf_f(in[i]);
}

// concat qw|kw rows (512x256) + qb|kb (512), tf32-round weights
__global__ void round_concat_qk(const float* __restrict__ qw,
                                const float* __restrict__ kw,
                                const float* __restrict__ qb,
                                const float* __restrict__ kb,
                                float* __restrict__ wdst,
                                float* __restrict__ bdst)
{
    int i = blockIdx.x * 256 + threadIdx.x;
    int total = 512 * C_;
    if (i < total) {
        int n = i >> 8;   // /256
        wdst[i] = f2tf_f(n < C_ ? qw[i] : kw[i - C_ * C_]);
    }
    if (i < 512) bdst[i] = (i < C_) ? qb[i] : kb[i - C_];
}

// ---------------------------------------------------------------------------
// Kernel: timestep embedding MLP + fused add-vector
// ---------------------------------------------------------------------------
__global__ void temb_kernel(const int* __restrict__ t,
                            const float* __restrict__ z0,
                            const float* __restrict__ zt,
                            const float* __restrict__ tw1, const float* __restrict__ tb1,
                            const float* __restrict__ tw2, const float* __restrict__ tb2,
                            const float* __restrict__ tpw, const float* __restrict__ tpb,
                            const float* __restrict__ zpw, const float* __restrict__ zpb)
{
    __shared__ float se[128];
    __shared__ float s1[512];
    __shared__ float s2[512];
    __shared__ float sz[256];

    int b = blockIdx.x, tid = threadIdx.x;

    if (tid < 64) {
        float f = expf((float)tid * (-logf(10000.f) / 63.f));
        float a = (float)t[b] * f;
        se[tid]      = sinf(a);
        se[64 + tid] = cosf(a);
    }
    if (tid < 128) {
        sz[tid]       = silu_f(z0[b * ZD_ + tid]);
        sz[128 + tid] = silu_f(zt[b * ZD_ + tid]);
    }
    __syncthreads();

    {
        float acc = tb1[tid];
        #pragma unroll 8
        for (int i = 0; i < 128; i++) acc += se[i] * tw1[i * TEMB_ + tid];
        s1[tid] = silu_f(acc);
    }
    __syncthreads();
    {
        float acc = tb2[tid];
        #pragma unroll 8
        for (int k = 0; k < 512; k++) acc += s1[k] * tw2[k * TEMB_ + tid];
        s2[tid] = silu_f(acc);
    }
    __syncthreads();

    if (tid < C_) {
        float acc = tpb[tid] + 2.f * zpb[tid];
        #pragma unroll 8
        for (int j = 0; j < 512; j++) acc += s2[j] * tpw[j * C_ + tid];
        #pragma unroll 8
        for (int i = 0; i < 128; i++) acc += (sz[i] + sz[128 + i]) * zpw[i * C_ + tid];
        g_add[b * C_ + tid] = acc;
    }
}

// ---------------------------------------------------------------------------
// Kernel: per-(b,c) channel norm over L, fused silu + tf32 round (conv input).
// ---------------------------------------------------------------------------
__global__ __launch_bounds__(256) void norm_kernel(const float* __restrict__ in,
                                                   float* __restrict__ out,
                                                   const float* __restrict__ gam,
                                                   const float* __restrict__ bet)
{
    __shared__ float red[64];
    int row = blockIdx.x, tid = threadIdx.x;
    const float4* p4 = (const float4*)(in + (size_t)row * L_);

    float4 a = p4[tid];
    float4 b = p4[tid + 256];
    float v[8] = { a.x, a.y, a.z, a.w, b.x, b.y, b.z, b.w };
    float s = 0.f, sq = 0.f;
    #pragma unroll
    for (int i = 0; i < 8; i++) { s += v[i]; sq += v[i] * v[i]; }

    #pragma unroll
    for (int o = 16; o > 0; o >>= 1) {
        s  += __shfl_down_sync(0xffffffffu, s,  o);
        sq += __shfl_down_sync(0xffffffffu, sq, o);
    }
    if ((tid & 31) == 0) { red[tid >> 5] = s; red[8 + (tid >> 5)] = sq; }
    __syncthreads();
    if (tid < 32) {
        float aa = (tid < 8) ? red[tid]     : 0.f;
        float b2 = (tid < 8) ? red[8 + tid] : 0.f;
        #pragma unroll
        for (int o = 4; o > 0; o >>= 1) {
            aa += __shfl_down_sync(0xffffffffu, aa, o);
            b2 += __shfl_down_sync(0xffffffffu, b2, o);
        }
        if (tid == 0) { red[32] = aa; red[33] = b2; }
    }
    __syncthreads();

    float mean = red[32] * (1.f / L_);
    float var  = red[33] * (1.f / L_) - mean * mean;
    float rstd = rsqrtf(var + 1e-6f);
    int c = row & (C_ - 1);
    float gm = gam[c], bt = bet[c];

    float4* q4 = (float4*)(out + (size_t)row * L_);
    float o8[8];
    #pragma unroll
    for (int i = 0; i < 8; i++) {
        float y = (v[i] - mean) * rstd * gm + bt;
        o8[i] = f2tf_f(y / (1.f + expf(-y)));
    }
    q4[tid]       = make_float4(o8[0], o8[1], o8[2], o8[3]);
    q4[tid + 256] = make_float4(o8[4], o8[5], o8[6], o8[7]);
}

// ---------------------------------------------------------------------------
// Kernel: per-(b,c) norm statistics -> fold factors (fA, fB) for stage 3.
// ---------------------------------------------------------------------------
__global__ __launch_bounds__(256) void stats_kernel(const float* __restrict__ in,
                                                    const float* __restrict__ gam,
                                                    const float* __restrict__ bet,
                                                    float2* __restrict__ st)
{
    __shared__ float red[64];
    int row = blockIdx.x, tid = threadIdx.x;
    const float4* p4 = (const float4*)(in + (size_t)row * L_);

    float4 a = p4[tid];
    float4 b = p4[tid + 256];
    float s  = a.x + a.y + a.z + a.w + b.x + b.y + b.z + b.w;
    float sq = a.x * a.x + a.y * a.y + a.z * a.z + a.w * a.w
             + b.x * b.x + b.y * b.y + b.z * b.z + b.w * b.w;

    #pragma unroll
    for (int o = 16; o > 0; o >>= 1) {
        s  += __shfl_down_sync(0xffffffffu, s,  o);
        sq += __shfl_down_sync(0xffffffffu, sq, o);
    }
    if ((tid & 31) == 0) { red[tid >> 5] = s; red[8 + (tid >> 5)] = sq; }
    __syncthreads();
    if (tid == 0) {
        float S = 0.f, SQ = 0.f;
        #pragma unroll
        for (int i = 0; i < 8; i++) { S += red[i]; SQ += red[8 + i]; }
        float mean = S * (1.f / L_);
        float var  = SQ * (1.f / L_) - mean * mean;
        float rstd = rsqrtf(var + 1e-6f);
        int c = row & (C_ - 1);
        float fA = rstd * gam[c];
        st[row] = make_float2(fA, bet[c] - mean * fA);
    }
}

// ---------------------------------------------------------------------------
// Kernel: fused norm + 32x32 transpose, [B][C][L] -> [B][L][C], tf32 out.
// ---------------------------------------------------------------------------
__global__ __launch_bounds__(256) void transpose_norm(const float* __restrict__ in,
                                                      const float2* __restrict__ st,
                                                      float* __restrict__ out)
{
    __shared__ float tile[32][33];
    int b = blockIdx.z;
    int l0 = blockIdx.x * 32, c0 = blockIdx.y * 32;
    int tx = threadIdx.x & 31, ty = threadIdx.x >> 5;
    #pragma unroll
    for (int i = 0; i < 4; i++) {
        int c = c0 + ty + i * 8;
        float2 f = st[b * C_ + c];
        float x = in[((size_t)(b * C_ + c)) * L_ + l0 + tx];
        tile[ty + i * 8][tx] = f2tf_f(fmaf(x, f.x, f.y));
    }
    __syncthreads();
    #pragma unroll
    for (int i = 0; i < 4; i++) {
        int l = l0 + ty + i * 8;
        out[((size_t)b * L_ + l) * C_ + c0 + tx] = tile[tx][ty + i * 8];
    }
}

// ---------------------------------------------------------------------------
// tf32 tensor-core GEMM — cp.async 3-STAGE pipeline, k-tile 32,
// FORCED 2 CTAs/SM via __launch_bounds__(256, 2).
//   C[m][n] = alpha * sum_k A[m][k] * B[n][k]  (generalized lda/ldb/ldc)
// Operands MUST be tf32-representable (pre-rounded).
// BIAS_MODE: 0 none, 1 per-m, 2 per-n. RES: fp32 residual. OTF32: round out.
// ---------------------------------------------------------------------------
constexpr int GEMM_SMEM = 3 * 2 * 128 * 36 * 4;   // 110592 B; x2 CTAs = 221 KB

template <int BIAS_MODE, bool RES, bool OTF32>
__global__ __launch_bounds__(256, 2) void gemm_tf32(
    const float* __restrict__ A, const float* __restrict__ Bm,
    const float* __restrict__ bias, const float* __restrict__ res,
    float* __restrict__ Cout, int K, int lda, int ldb, int ldc,
    float alpha, size_t strideA, size_t strideB, size_t strideC)
{
    extern __shared__ float smem[];
    float (*sA)[128][36] = (float(*)[128][36])smem;                    // [stage]
    float (*sB)[128][36] = (float(*)[128][36])(smem + 3 * 128 * 36);

    int bz = blockIdx.z;
    A  += strideA * bz;
    Bm += strideB * bz;

    int m0 = blockIdx.y * 128, n0 = blockIdx.x * 128;
    int tid = threadIdx.x, lane = tid & 31, w = tid >> 5;
    int wm = (w & 3) * 32, wn = (w >> 2) * 64;
    int g = lane >> 2, tg = lane & 3;

    int crow[4], cseg[4];
    #pragma unroll
    for (int it = 0; it < 4; it++) {
        int idx = tid + it * 256;
        crow[it] = idx >> 3;
        cseg[it] = (idx & 7) * 4;
    }

    float acc[2][8][4] = {};
    int KT = K / 32;

    auto issue = [&](int kt, int stg) {
        int kk = kt * 32;
        #pragma unroll
        for (int it = 0; it < 4; it++) {
            CP_ASYNC16(smem_u32(&sA[stg][crow[it]][cseg[it]]),
                       &A[(size_t)(m0 + crow[it]) * lda + kk + cseg[it]]);
            CP_ASYNC16(smem_u32(&sB[stg][crow[it]][cseg[it]]),
                       &Bm[(size_t)(n0 + crow[it]) * ldb + kk + cseg[it]]);
        }
    };

    issue(0, 0); CP_COMMIT();
    issue(1, 1); CP_COMMIT();

    for (int kt = 0; kt < KT; kt++) {
        int st = kt % 3;
        if (kt + 2 < KT) { issue(kt + 2, (kt + 2) % 3); CP_COMMIT(); CP_WAIT2(); }
        else if (kt + 1 < KT) { CP_WAIT1(); }
        else { CP_WAIT0(); }
        __syncthreads();

        #pragma unroll
        for (int ks = 0; ks < 4; ks++) {
            int kb = ks * 8 + tg;
            u32 afr[2][4], bfr[8][2];
            #pragma unroll
            for (int mt = 0; mt < 2; mt++) {
                int r = wm + mt * 16 + g;
                afr[mt][0] = __float_as_uint(sA[st][r][kb]);
                afr[mt][1] = __float_as_uint(sA[st][r + 8][kb]);
                afr[mt][2] = __float_as_uint(sA[st][r][kb + 4]);
                afr[mt][3] = __float_as_uint(sA[st][r + 8][kb + 4]);
            }
            #pragma unroll
            for (int nt = 0; nt < 8; nt++) {
                int c = wn + nt * 8 + g;
                bfr[nt][0] = __float_as_uint(sB[st][c][kb]);
                bfr[nt][1] = __float_as_uint(sB[st][c][kb + 4]);
            }
            #pragma unroll
            for (int mt = 0; mt < 2; mt++)
                #pragma unroll
                for (int nt = 0; nt < 8; nt++)
                    MMA_TF32(acc[mt][nt], afr[mt], bfr[nt]);
        }
        __syncthreads();
    }

    #pragma unroll
    for (int mt = 0; mt < 2; mt++) {
        #pragma unroll
        for (int half = 0; half < 2; half++) {
            int m = m0 + wm + mt * 16 + g + half * 8;
            float bm = (BIAS_MODE == 1) ? bias[m] : 0.f;
            #pragma unroll
            for (int nt = 0; nt < 8; nt++) {
                int n = n0 + wn + nt * 8 + tg * 2;
                float v0 = acc[mt][nt][half * 2 + 0] * alpha;
                float v1 = acc[mt][nt][half * 2 + 1] * alpha;
                if (BIAS_MODE == 1) { v0 += bm; v1 += bm; }
                if (BIAS_MODE == 2) { v0 += bias[n]; v1 += bias[n + 1]; }
                size_t off = strideC * bz + (size_t)m * ldc + n;
                if (RES) {
                    float2 r2 = *(const float2*)&res[off];
                    v0 += r2.x; v1 += r2.y;
                }
                if (OTF32) { v0 = f2tf_f(v0); v1 = f2tf_f(v1); }
                *(float2*)&Cout[off] = make_float2(v0, v1);
            }
        }
    }
}

// ---------------------------------------------------------------------------
// tf32 tensor-core 3-tap conv (implicit GEMM) — cp.async 2-stage pipelined
// (unchanged from R10 WIN). 2 CTAs/SM forced.
// ---------------------------------------------------------------------------
constexpr int CONV_SMEM = (2 * 128 * 52 + 2 * 16 * 144 + 128 * 52) * 4;

template <bool ADDV, bool RES>
__global__ __launch_bounds__(256, 2) void conv_tf32(
    const float* __restrict__ in,   // [B][C][L] (tf32 values)
    const float* __restrict__ w,    // [C][768]  (tf32 values)
    const float* __restrict__ bias,
    const float* __restrict__ addv,
    const float* __restrict__ resid,
    float* __restrict__ out)
{
    extern __shared__ float smemc[];
    float (*sW)[128][52] = (float(*)[128][52])smemc;                 // [stage]
    float (*sR)[16][144] = (float(*)[16][144])(smemc + 2 * 128 * 52);
    float (*sP)[52]      = (float(*)[52])(smemc + 2 * 128 * 52 + 2 * 16 * 144);

    int b  = blockIdx.z;
    int m0 = blockIdx.y * 128;
    int l0 = blockIdx.x * 128;
    int tid = threadIdx.x, lane = tid & 31, wid = tid >> 5;
    int wm = (wid & 3) * 32, wn = (wid >> 2) * 64;
    int g = lane >> 2, tg = lane & 3;

    auto issue_stage = [&](int kt, int stg) {
        int k0 = kt * 48, ci0 = kt * 16;
        #pragma unroll
        for (int it = 0; it < 6; it++) {
            int idx = tid + it * 256;
            int row = idx / 12, seg = (idx % 12) * 4;
            CP_ASYNC16(smem_u32(&sW[stg][row][seg]),
                       &w[(size_t)(m0 + row) * 768 + k0 + seg]);
        }
        for (int idx = tid; idx < 16 * 36; idx += 256) {
            int c = idx / 36, ch = (idx % 36) * 4;
            int l = l0 - 8 + ch;
            if (l >= 0 && l + 3 < L_) {
                CP_ASYNC16(smem_u32(&sR[stg][c][ch]),
                           &in[((size_t)(b * C_ + ci0 + c)) * L_ + l]);
            } else {
                *(float4*)&sR[stg][c][ch] = make_float4(0.f, 0.f, 0.f, 0.f);
            }
        }
    };

    float acc[2][8][4] = {};

    issue_stage(0, 0);
    CP_COMMIT();

    for (int kt = 0; kt < 16; kt++) {
        int st = kt & 1;
        CP_WAIT0();
        __syncthreads();

        for (int idx = tid; idx < 16 * 132; idx += 256) {
            int c = idx / 132, p = idx % 132;
            if (p < 130) {
                float v = sR[st][c][p + 7];
                #pragma unroll
                for (int t_ = 0; t_ < 3; t_++) {
                    int j = p - t_;
                    if (j >= 0 && j < 128) sP[j][3 * c + t_] = v;
                }
            }
        }
        if (kt + 1 < 16) { issue_stage(kt + 1, st ^ 1); CP_COMMIT(); }
        __syncthreads();

        #pragma unroll
        for (int ks = 0; ks < 6; ks++) {
            int kb = ks * 8 + tg;
            u32 afr[2][4], bfr[8][2];
            #pragma unroll
            for (int mt = 0; mt < 2; mt++) {
                int r = wm + mt * 16 + g;
                afr[mt][0] = __float_as_uint(sW[st][r][kb]);
                afr[mt][1] = __float_as_uint(sW[st][r + 8][kb]);
                afr[mt][2] = __float_as_uint(sW[st][r][kb + 4]);
                afr[mt][3] = __float_as_uint(sW[st][r + 8][kb + 4]);
            }
            #pragma unroll
            for (int nt = 0; nt < 8; nt++) {
                int c = wn + nt * 8 + g;
                bfr[nt][0] = __float_as_uint(sP[c][kb]);
                bfr[nt][1] = __float_as_uint(sP[c][kb + 4]);
            }
            #pragma unroll
            for (int mt = 0; mt < 2; mt++)
                #pragma unroll
                for (int nt = 0; nt < 8; nt++)
                    MMA_TF32(acc[mt][nt], afr[mt], bfr[nt]);
        }
    }

    #pragma unroll
    for (int mt = 0; mt < 2; mt++) {
        #pragma unroll
        for (int half = 0; half < 2; half++) {
            int m = m0 + wm + mt * 16 + g + half * 8;
            float base = bias[m];
            if (ADDV) base += addv[b * C_ + m];
            #pragma unroll
            for (int nt = 0; nt < 8; nt++) {
                int n = l0 + wn + nt * 8 + tg * 2;
                float v0 = acc[mt][nt][half * 2 + 0] + base;
                float v1 = acc[mt][nt][half * 2 + 1] + base;
                size_t off = ((size_t)(b * C_ + m)) * L_ + n;
                if (RES) {
                    float2 r2 = *(const float2*)&resid[off];
                    v0 += r2.x; v1 += r2.y;
                }
                *(float2*)&out[off] = make_float2(v0, v1);
            }
        }
    }
}

// ---------------------------------------------------------------------------
// Row softmax in-place — 2 rows per block, 128 threads/row, 4 independent
// float4 loads per thread (MLP 4), __expf, tf32-round on store.
// ---------------------------------------------------------------------------
__global__ __launch_bounds__(256) void softmax_kernel(float* __restrict__ w)
{
    __shared__ float red [2][4];
    __shared__ float red2[2][4];
    int tid  = threadIdx.x;
    int half = tid >> 7;            // which of the 2 rows
    int t    = tid & 127;
    int wh   = (tid >> 5) & 3;      // warp index within the half (0..3)
    size_t row = (size_t)blockIdx.x * 2 + half;
    float4* p4 = (float4*)(w + row * (size_t)L_);

    float4 va = p4[t], vb = p4[t + 128], vc = p4[t + 256], vd = p4[t + 384];
    float v[16] = { va.x, va.y, va.z, va.w, vb.x, vb.y, vb.z, vb.w,
                    vc.x, vc.y, vc.z, vc.w, vd.x, vd.y, vd.z, vd.w };

    float mx = v[0];
    #pragma unroll
    for (int i = 1; i < 16; i++) mx = fmaxf(mx, v[i]);
    #pragma unroll
    for (int o = 16; o > 0; o >>= 1) mx = fmaxf(mx, __shfl_xor_sync(0xffffffffu, mx, o));
    if ((tid & 31) == 0) red[half][wh] = mx;
    __syncthreads();
    float m = fmaxf(fmaxf(red[half][0], red[half][1]),
                    fmaxf(red[half][2], red[half][3]));

    float s = 0.f;
    #pragma unroll
    for (int i = 0; i < 16; i++) { v[i] = __expf(v[i] - m); s += v[i]; }
    #pragma unroll
    for (int o = 16; o > 0; o >>= 1) s += __shfl_xor_sync(0xffffffffu, s, o);
    if ((tid & 31) == 0) red2[half][wh] = s;
    __syncthreads();
    float inv = 1.f / (red2[half][0] + red2[half][1] + red2[half][2] + red2[half][3]);

    float4 o4;
    o4.x = f2tf_f(v[0]  * inv); o4.y = f2tf_f(v[1]  * inv);
    o4.z = f2tf_f(v[2]  * inv); o4.w = f2tf_f(v[3]  * inv);
    p4[t] = o4;
    o4.x = f2tf_f(v[4]  * inv); o4.y = f2tf_f(v[5]  * inv);
    o4.z = f2tf_f(v[6]  * inv); o4.w = f2tf_f(v[7]  * inv);
    p4[t + 128] = o4;
    o4.x = f2tf_f(v[8]  * inv); o4.y = f2tf_f(v[9]  * inv);
    o4.z = f2tf_f(v[10] * inv); o4.w = f2tf_f(v[11] * inv);
    p4[t + 256] = o4;
    o4.x = f2tf_f(v[12] * inv); o4.y = f2tf_f(v[13] * inv);
    o4.z = f2tf_f(v[14] * inv); o4.w = f2tf_f(v[15] * inv);
    p4[t + 384] = o4;
}

// ---------------------------------------------------------------------------
// Host orchestration (graph-capturable: kernel launches only)
// ---------------------------------------------------------------------------
extern "C" void kernel_launch(void* const* d_in, const int* in_sizes, int n_in,
                              void* d_out, int out_size)
{
    (void)in_sizes; (void)n_in; (void)out_size;

    const float* x   = (const float*)d_in[0];
    const int*   t   = (const int*)  d_in[1];
    const float* z0  = (const float*)d_in[2];
    const float* zt  = (const float*)d_in[3];
    const float* tw1 = (const float*)d_in[4];
    const float* tb1 = (const float*)d_in[5];
    const float* tw2 = (const float*)d_in[6];
    const float* tb2 = (const float*)d_in[7];
    const float* tpw = (const float*)d_in[8];
    const float* tpb = (const float*)d_in[9];
    const float* zpw = (const float*)d_in[10];
    const float* zpb = (const float*)d_in[11];
    const float* n1g = (const float*)d_in[12];
    const float* n1b = (const float*)d_in[13];
    const float* n2g = (const float*)d_in[14];
    const float* n2b = (const float*)d_in[15];
    const float* ng  = (const float*)d_in[16];
    const float* nb  = (const float*)d_in[17];
    const float* c1w = (const float*)d_in[18];
    const float* c1b = (const float*)d_in[19];
    const float* c2w = (const float*)d_in[20];
    const float* c2b = (const float*)d_in[21];
    const float* qw  = (const float*)d_in[22];
    const float* qb  = (const float*)d_in[23];
    const float* kw  = (const float*)d_in[24];
    const float* kb  = (const float*)d_in[25];
    const float* vw  = (const float*)d_in[26];
    const float* vb  = (const float*)d_in[27];
    const float* pw  = (const float*)d_in[28];
    const float* pb  = (const float*)d_in[29];
    float* out = (float*)d_out;

    float *p_t1, *p_h, *p_x1, *p_hnT, *p_qk, *p_v, *p_h2T, *p_sc, *p_add, *p_wr;
    float2* p_st;
    cudaGetSymbolAddress((void**)&p_t1,  g_t1);
    cudaGetSymbolAddress((void**)&p_h,   g_h);
    cudaGetSymbolAddress((void**)&p_x1,  g_x1);
    cudaGetSymbolAddress((void**)&p_hnT, g_hnT);
    cudaGetSymbolAddress((void**)&p_qk,  g_qk);
    cudaGetSymbolAddress((void**)&p_v,   g_v);
    cudaGetSymbolAddress((void**)&p_h2T, g_h2T);
    cudaGetSymbolAddress((void**)&p_sc,  g_sc);
    cudaGetSymbolAddress((void**)&p_add, g_add);
    cudaGetSymbolAddress((void**)&p_wr,  g_wr);
    cudaGetSymbolAddress((void**)&p_st,  g_st);

    float* wr_qk  = p_wr;                                    // [512][256]
    float* wr_v   = p_wr + 512 * C_;                         // [256][256]
    float* wr_p   = wr_v + C_ * C_;                          // [256][256]
    float* wr_c1  = wr_p + C_ * C_;                          // [256][768]
    float* wr_c2  = wr_c1 + C_ * C_ * 3;                     // [256][768]
    float* b_qk   = wr_c2 + C_ * C_ * 3;                     // [512]

    // dynamic-smem attributes (host-side, idempotent)
    cudaFuncSetAttribute(gemm_tf32<2, false, true>,
                         cudaFuncAttributeMaxDynamicSharedMemorySize, GEMM_SMEM);
    cudaFuncSetAttribute(gemm_tf32<1, false, true>,
                         cudaFuncAttributeMaxDynamicSharedMemorySize, GEMM_SMEM);
    cudaFuncSetAttribute(gemm_tf32<0, false, false>,
                         cudaFuncAttributeMaxDynamicSharedMemorySize, GEMM_SMEM);
    cudaFuncSetAttribute(gemm_tf32<0, false, true>,
                         cudaFuncAttributeMaxDynamicSharedMemorySize, GEMM_SMEM);
    cudaFuncSetAttribute(gemm_tf32<1, true, false>,
                         cudaFuncAttributeMaxDynamicSharedMemorySize, GEMM_SMEM);
    cudaFuncSetAttribute(conv_tf32<true, false>,
                         cudaFuncAttributeMaxDynamicSharedMemorySize, CONV_SMEM);
    cudaFuncSetAttribute(conv_tf32<false, true>,
                         cudaFuncAttributeMaxDynamicSharedMemorySize, CONV_SMEM);

    const size_t sCL  = (size_t)C_ * L_;    // [B,C,L] / [B,L,C] batch stride
    const size_t sQK  = (size_t)L_ * 512;   // [B,L,512] batch stride
    const size_t sLL  = (size_t)L_ * L_;    // [B,L,L] batch stride

    dim3 gconv(L_ / 128, C_ / 128, B_);

    // weight prep + temb
    round_tf32_kernel<<<(C_ * C_ * 3 + 255) / 256, 256>>>(c1w, wr_c1, C_ * C_ * 3);
    round_tf32_kernel<<<(C_ * C_ * 3 + 255) / 256, 256>>>(c2w, wr_c2, C_ * C_ * 3);
    temb_kernel<<<B_, 512>>>(t, z0, zt, tw1, tb1, tw2, tb2, tpw, tpb, zpw, zpb);
    round_concat_qk<<<(512 * C_ + 255) / 256, 256>>>(qw, kw, qb, kb, wr_qk, b_qk);
    round_tf32_kernel<<<(C_ * C_ + 255) / 256, 256>>>(vw, wr_v, C_ * C_);
    round_tf32_kernel<<<(C_ * C_ + 255) / 256, 256>>>(pw, wr_p, C_ * C_);

    // stage 1: t1 = tf32(silu(chan_norm(x, n1))); h = conv1(t1) + add
    norm_kernel<<<B_ * C_, 256>>>(x, p_t1, n1g, n1b);
    conv_tf32<true, false><<<gconv, 256, CONV_SMEM>>>(p_t1, wr_c1, c1b,
                                                      p_add, nullptr, p_h);

    // stage 2: t1 = tf32(silu(chan_norm(h, n2))); x1 = x + conv2(t1)
    norm_kernel<<<B_ * C_, 256>>>(p_h, p_t1, n2g, n2b);
    conv_tf32<false, true><<<gconv, 256, CONV_SMEM>>>(p_t1, wr_c2, c2b,
                                                      nullptr, x, p_x1);

    // stage 3: stats(x1, n) -> fused norm+transpose -> hnT [B][L][C] tf32
    stats_kernel<<<B_ * C_, 256>>>(p_x1, ng, nb, p_st);
    dim3 gtr(L_ / 32, C_ / 32, B_);
    transpose_norm<<<gtr, 256>>>(p_x1, p_st, p_hnT);

    // qk [L][512] = hnT @ [qw;kw]^T + b(per-n)    M=L, N=512, K=256
    dim3 gqk(512 / 128, L_ / 128, B_);
    gemm_tf32<2, false, true><<<gqk, 256, GEMM_SMEM>>>(
        p_hnT, wr_qk, b_qk, nullptr, p_qk,
        C_, C_, C_, 512, 1.f, sCL, 0, sQK);
    // v [C][L] = vw @ hn + b(per-m)               M=C, N=L, K=256
    dim3 gv(L_ / 128, C_ / 128, B_);
    gemm_tf32<1, false, true><<<gv, 256, GEMM_SMEM>>>(
        wr_v, p_hnT, vb, nullptr, p_v,
        C_, C_, C_, L_, 1.f, 0, sCL, sCL);

    // scores[i][j] = (1/16) q[i]·k[j]             M=N=L, K=256 (ld 512)
    dim3 gsc(L_ / 128, L_ / 128, B_);
    gemm_tf32<0, false, false><<<gsc, 256, GEMM_SMEM>>>(
        p_qk, p_qk + 256, nullptr, nullptr, p_sc,
        C_, 512, 512, L_, 0.0625f, sQK, sQK, sLL);

    // softmax over j (in place, tf32 out) — 2 rows per block
    softmax_kernel<<<B_ * L_ / 2, 256>>>(p_sc);

    // h2T[i][c] = sum_j sc[i][j] v[c][j]          M=L, N=C, K=L
    dim3 gh2(C_ / 128, L_ / 128, B_);
    gemm_tf32<0, false, true><<<gh2, 256, GEMM_SMEM>>>(
        p_sc, p_v, nullptr, nullptr, p_h2T,
        L_, L_, L_, C_, 1.f, sLL, sCL, sCL);

    // out[c][l] = pw @ h2 + pb + x1               M=C, N=L, K=256
    dim3 gpr(L_ / 128, C_ / 128, B_);
    gemm_tf32<1, true, false><<<gpr, 256, GEMM_SMEM>>>(
        wr_p, p_h2T, pb, p_x1, out,
        C_, C_, C_, L_, 1.f, 0, sCL, sCL);
}

// round 13
// speedup vs baseline: 1.4092x; 1.4092x over previous
#include <cuda_runtime.h>
#include <cuda_fp16.h>
#include <math.h>
#include <stdint.h>

typedef unsigned int u32;

// ---------------------------------------------------------------------------
// Problem constants
// ---------------------------------------------------------------------------
constexpr int B_    = 16;
constexpr int C_    = 256;
constexpr int L_    = 2048;
constexpr int ZD_   = 128;
constexpr int TEMB_ = 512;
constexpr size_t BCL = (size_t)B_ * C_ * L_;
constexpr size_t BLL = (size_t)B_ * L_ * L_;

// ---------------------------------------------------------------------------
// Scratch (device globals; allocation-free per harness rules)
// ---------------------------------------------------------------------------
__device__ __align__(16) __half  g_t1 [BCL];                    // silu(norm(.)) fp16
__device__ __align__(16) float   g_h  [BCL];                    // conv1 output
__device__ __align__(16) float   g_x1 [BCL];                    // x + conv2(...)
__device__ __align__(16) __half  g_hnT[BCL];                    // norm(x1)^T [B][L][C]
__device__ __align__(16) __half  g_qk [(size_t)B_ * L_ * 512];  // q|k fused [B][L][512]
__device__ __align__(16) __half  g_v  [BCL];                    // v [B][C][L]
__device__ __align__(16) __half  g_h2T[BCL];                    // attn out [B][L][C]
__device__ __align__(16) float   g_sc [BLL];                    // scores fp32
__device__ __align__(16) __half  g_wS [BLL];                    // softmax weights fp16
__device__ __align__(16) float   g_add[B_ * C_];                // temb/z projection
__device__ __align__(16) float2  g_st [B_ * C_];                // norm fold (fA, fB)
// fp16 weights: qk(512x256) | vw | pw | c1w | c2w
__device__ __align__(16) __half g_wrh[512 * C_ + 2 * C_ * C_ + 2 * C_ * C_ * 3];
__device__ __align__(16) float  g_bqk[512];                     // qb|kb bias

static __device__ __forceinline__ float silu_f(float x) {
    return x / (1.f + expf(-x));
}

#define MMA_F16(d, a, b)                                                      \
    asm volatile("mma.sync.aligned.m16n8k16.row.col.f32.f16.f16.f32 "         \
                 "{%0,%1,%2,%3},{%4,%5,%6,%7},{%8,%9},{%0,%1,%2,%3};"         \
                 : "+f"(d[0]), "+f"(d[1]), "+f"(d[2]), "+f"(d[3])             \
                 : "r"(a[0]), "r"(a[1]), "r"(a[2]), "r"(a[3]),                \
                   "r"(b[0]), "r"(b[1]))

#define CP_ASYNC16(dst_u32, src_ptr)                                          \
    asm volatile("cp.async.cg.shared.global [%0], [%1], 16;"                  \
                 :: "r"(dst_u32), "l"(src_ptr))
#define CP_COMMIT()  asm volatile("cp.async.commit_group;")
#define CP_WAIT0()   asm volatile("cp.async.wait_group 0;")
#define CP_WAIT1()   asm volatile("cp.async.wait_group 1;")

static __device__ __forceinline__ u32 smem_u32(const void* p) {
    return (u32)__cvta_generic_to_shared(p);
}

// ---------------------------------------------------------------------------
// Weight prep kernels (tiny, run once per launch)
// ---------------------------------------------------------------------------
__global__ void round_f16_kernel(const float* __restrict__ in,
                                 __half* __restrict__ out, int n)
{
    int i = blockIdx.x * 256 + threadIdx.x;
    if (i < n) out[i] = __float2half_rn(in[i]);
}

// concat qw|kw rows (512x256) + qb|kb (512), fp16 weights, fp32 bias
__global__ void concat_qk(const float* __restrict__ qw,
                          const float* __restrict__ kw,
                          const float* __restrict__ qb,
                          const float* __restrict__ kb,
                          __half* __restrict__ wdst,
                          float* __restrict__ bdst)
{
    int i = blockIdx.x * 256 + threadIdx.x;
    int total = 512 * C_;
    if (i < total) {
        int n = i >> 8;   // /256
        wdst[i] = __float2half_rn(n < C_ ? qw[i] : kw[i - C_ * C_]);
    }
    if (i < 512) bdst[i] = (i < C_) ? qb[i] : kb[i - C_];
}

// ---------------------------------------------------------------------------
// Kernel: timestep embedding MLP + fused add-vector (fp32, tiny)
// ---------------------------------------------------------------------------
__global__ void temb_kernel(const int* __restrict__ t,
                            const float* __restrict__ z0,
                            const float* __restrict__ zt,
                            const float* __restrict__ tw1, const float* __restrict__ tb1,
                            const float* __restrict__ tw2, const float* __restrict__ tb2,
                            const float* __restrict__ tpw, const float* __restrict__ tpb,
                            const float* __restrict__ zpw, const float* __restrict__ zpb)
{
    __shared__ float se[128];
    __shared__ float s1[512];
    __shared__ float s2[512];
    __shared__ float sz[256];

    int b = blockIdx.x, tid = threadIdx.x;

    if (tid < 64) {
        float f = expf((float)tid * (-logf(10000.f) / 63.f));
        float a = (float)t[b] * f;
        se[tid]      = sinf(a);
        se[64 + tid] = cosf(a);
    }
    if (tid < 128) {
        sz[tid]       = silu_f(z0[b * ZD_ + tid]);
        sz[128 + tid] = silu_f(zt[b * ZD_ + tid]);
    }
    __syncthreads();

    {
        float acc = tb1[tid];
        #pragma unroll 8
        for (int i = 0; i < 128; i++) acc += se[i] * tw1[i * TEMB_ + tid];
        s1[tid] = silu_f(acc);
    }
    __syncthreads();
    {
        float acc = tb2[tid];
        #pragma unroll 8
        for (int k = 0; k < 512; k++) acc += s1[k] * tw2[k * TEMB_ + tid];
        s2[tid] = silu_f(acc);
    }
    __syncthreads();

    if (tid < C_) {
        float acc = tpb[tid] + 2.f * zpb[tid];
        #pragma unroll 8
        for (int j = 0; j < 512; j++) acc += s2[j] * tpw[j * C_ + tid];
        #pragma unroll 8
        for (int i = 0; i < 128; i++) acc += (sz[i] + sz[128 + i]) * zpw[i * C_ + tid];
        g_add[b * C_ + tid] = acc;
    }
}

// ---------------------------------------------------------------------------
// Kernel: per-(b,c) channel norm over L, fused silu, fp16 output (conv input).
// ---------------------------------------------------------------------------
__global__ __launch_bounds__(256) void norm_kernel(const float* __restrict__ in,
                                                   __half* __restrict__ out,
                                                   const float* __restrict__ gam,
                                                   const float* __restrict__ bet)
{
    __shared__ float red[64];
    int row = blockIdx.x, tid = threadIdx.x;
    const float4* p4 = (const float4*)(in + (size_t)row * L_);

    float4 a = p4[tid];
    float4 b = p4[tid + 256];
    float v[8] = { a.x, a.y, a.z, a.w, b.x, b.y, b.z, b.w };
    float s = 0.f, sq = 0.f;
    #pragma unroll
    for (int i = 0; i < 8; i++) { s += v[i]; sq += v[i] * v[i]; }

    #pragma unroll
    for (int o = 16; o > 0; o >>= 1) {
        s  += __shfl_down_sync(0xffffffffu, s,  o);
        sq += __shfl_down_sync(0xffffffffu, sq, o);
    }
    if ((tid & 31) == 0) { red[tid >> 5] = s; red[8 + (tid >> 5)] = sq; }
    __syncthreads();
    if (tid < 32) {
        float aa = (tid < 8) ? red[tid]     : 0.f;
        float b2 = (tid < 8) ? red[8 + tid] : 0.f;
        #pragma unroll
        for (int o = 4; o > 0; o >>= 1) {
            aa += __shfl_down_sync(0xffffffffu, aa, o);
            b2 += __shfl_down_sync(0xffffffffu, b2, o);
        }
        if (tid == 0) { red[32] = aa; red[33] = b2; }
    }
    __syncthreads();

    float mean = red[32] * (1.f / L_);
    float var  = red[33] * (1.f / L_) - mean * mean;
    float rstd = rsqrtf(var + 1e-6f);
    int c = row & (C_ - 1);
    float gm = gam[c], bt = bet[c];

    float o8[8];
    #pragma unroll
    for (int i = 0; i < 8; i++) {
        float y = (v[i] - mean) * rstd * gm + bt;
        o8[i] = y / (1.f + expf(-y));
    }
    __half2* q2 = (__half2*)(out + (size_t)row * L_);
    q2[2 * tid + 0]       = __floats2half2_rn(o8[0], o8[1]);
    q2[2 * tid + 1]       = __floats2half2_rn(o8[2], o8[3]);
    q2[512 + 2 * tid + 0] = __floats2half2_rn(o8[4], o8[5]);
    q2[512 + 2 * tid + 1] = __floats2half2_rn(o8[6], o8[7]);
}

// ---------------------------------------------------------------------------
// Kernel: per-(b,c) norm statistics -> fold factors (fA, fB) for stage 3.
// ---------------------------------------------------------------------------
__global__ __launch_bounds__(256) void stats_kernel(const float* __restrict__ in,
                                                    const float* __restrict__ gam,
                                                    const float* __restrict__ bet,
                                                    float2* __restrict__ st)
{
    __shared__ float red[64];
    int row = blockIdx.x, tid = threadIdx.x;
    const float4* p4 = (const float4*)(in + (size_t)row * L_);

    float4 a = p4[tid];
    float4 b = p4[tid + 256];
    float s  = a.x + a.y + a.z + a.w + b.x + b.y + b.z + b.w;
    float sq = a.x * a.x + a.y * a.y + a.z * a.z + a.w * a.w
             + b.x * b.x + b.y * b.y + b.z * b.z + b.w * b.w;

    #pragma unroll
    for (int o = 16; o > 0; o >>= 1) {
        s  += __shfl_down_sync(0xffffffffu, s,  o);
        sq += __shfl_down_sync(0xffffffffu, sq, o);
    }
    if ((tid & 31) == 0) { red[tid >> 5] = s; red[8 + (tid >> 5)] = sq; }
    __syncthreads();
    if (tid == 0) {
        float S = 0.f, SQ = 0.f;
        #pragma unroll
        for (int i = 0; i < 8; i++) { S += red[i]; SQ += red[8 + i]; }
        float mean = S * (1.f / L_);
        float var  = SQ * (1.f / L_) - mean * mean;
        float rstd = rsqrtf(var + 1e-6f);
        int c = row & (C_ - 1);
        float fA = rstd * gam[c];
        st[row] = make_float2(fA, bet[c] - mean * fA);
    }
}

// ---------------------------------------------------------------------------
// Kernel: fused norm + 32x32 transpose, fp32 [B][C][L] -> fp16 [B][L][C].
// ---------------------------------------------------------------------------
__global__ __launch_bounds__(256) void transpose_norm(const float* __restrict__ in,
                                                      const float2* __restrict__ st,
                                                      __half* __restrict__ out)
{
    __shared__ float tile[32][33];
    int b = blockIdx.z;
    int l0 = blockIdx.x * 32, c0 = blockIdx.y * 32;
    int tx = threadIdx.x & 31, ty = threadIdx.x >> 5;
    #pragma unroll
    for (int i = 0; i < 4; i++) {
        int c = c0 + ty + i * 8;
        float2 f = st[b * C_ + c];
        float x = in[((size_t)(b * C_ + c)) * L_ + l0 + tx];
        tile[ty + i * 8][tx] = fmaf(x, f.x, f.y);
    }
    __syncthreads();
    #pragma unroll
    for (int i = 0; i < 4; i++) {
        int l = l0 + ty + i * 8;
        out[((size_t)b * L_ + l) * C_ + c0 + tx] = __float2half_rn(tile[tx][ty + i * 8]);
    }
}

// ---------------------------------------------------------------------------
// fp16 tensor-core GEMM (m16n8k16), cp.async 2-stage pipeline, k-tile 32,
// FORCED 2 CTAs/SM. Canonical NT: C[m][n] = alpha*sum_k A[m][k]*B[n][k].
// BIAS_MODE: 0 none, 1 per-m, 2 per-n. RES: fp32 residual. OHALF: out dtype.
// ---------------------------------------------------------------------------
constexpr int GEMM_SMEM = 2 * 2 * 128 * 56 * 2;   // 57344 B; x2 CTAs OK

template <int BIAS_MODE, bool RES, bool OHALF>
__global__ __launch_bounds__(256, 2) void gemm_f16(
    const __half* __restrict__ A, const __half* __restrict__ Bm,
    const float* __restrict__ bias, const float* __restrict__ res,
    void* __restrict__ Cout, int K, int lda, int ldb, int ldc,
    float alpha, size_t strideA, size_t strideB, size_t strideC)
{
    extern __shared__ __half hsm[];
    __half (*sA)[128][56] = (__half(*)[128][56])hsm;                 // [stage]
    __half (*sB)[128][56] = (__half(*)[128][56])(hsm + 2 * 128 * 56);

    int bz = blockIdx.z;
    A  += strideA * bz;
    Bm += strideB * bz;

    int m0 = blockIdx.y * 128, n0 = blockIdx.x * 128;
    int tid = threadIdx.x, lane = tid & 31, w = tid >> 5;
    int wm = (w & 3) * 32, wn = (w >> 2) * 64;
    int g = lane >> 2, tg = lane & 3;

    // copy coords: k-tile = 32 halves/row = 4 chunks of 8; 128 rows -> 512 chunks
    int crow[2], cseg[2];
    #pragma unroll
    for (int it = 0; it < 2; it++) {
        int idx = tid + it * 256;
        crow[it] = idx >> 2;
        cseg[it] = (idx & 3) * 8;
    }

    float acc[2][8][4] = {};
    int KT = K / 32;

    auto issue = [&](int kt, int stg) {
        int kk = kt * 32;
        #pragma unroll
        for (int it = 0; it < 2; it++) {
            CP_ASYNC16(smem_u32(&sA[stg][crow[it]][cseg[it]]),
                       &A[(size_t)(m0 + crow[it]) * lda + kk + cseg[it]]);
            CP_ASYNC16(smem_u32(&sB[stg][crow[it]][cseg[it]]),
                       &Bm[(size_t)(n0 + crow[it]) * ldb + kk + cseg[it]]);
        }
    };

    issue(0, 0); CP_COMMIT();

    for (int kt = 0; kt < KT; kt++) {
        int st = kt & 1;
        if (kt + 1 < KT) { issue(kt + 1, st ^ 1); CP_COMMIT(); CP_WAIT1(); }
        else             { CP_WAIT0(); }
        __syncthreads();

        #pragma unroll
        for (int ks = 0; ks < 2; ks++) {
            int kb = ks * 16 + tg * 2;
            u32 afr[2][4], bfr[8][2];
            #pragma unroll
            for (int mt = 0; mt < 2; mt++) {
                int r = wm + mt * 16 + g;
                afr[mt][0] = *(const u32*)&sA[st][r][kb];
                afr[mt][1] = *(const u32*)&sA[st][r + 8][kb];
                afr[mt][2] = *(const u32*)&sA[st][r][kb + 8];
                afr[mt][3] = *(const u32*)&sA[st][r + 8][kb + 8];
            }
            #pragma unroll
            for (int nt = 0; nt < 8; nt++) {
                int c = wn + nt * 8 + g;
                bfr[nt][0] = *(const u32*)&sB[st][c][kb];
                bfr[nt][1] = *(const u32*)&sB[st][c][kb + 8];
            }
            #pragma unroll
            for (int mt = 0; mt < 2; mt++)
                #pragma unroll
                for (int nt = 0; nt < 8; nt++)
                    MMA_F16(acc[mt][nt], afr[mt], bfr[nt]);
        }
        __syncthreads();
    }

    // epilogue
    #pragma unroll
    for (int mt = 0; mt < 2; mt++) {
        #pragma unroll
        for (int half = 0; half < 2; half++) {
            int m = m0 + wm + mt * 16 + g + half * 8;
            float bm = (BIAS_MODE == 1) ? bias[m] : 0.f;
            #pragma unroll
            for (int nt = 0; nt < 8; nt++) {
                int n = n0 + wn + nt * 8 + tg * 2;
                float v0 = acc[mt][nt][half * 2 + 0] * alpha;
                float v1 = acc[mt][nt][half * 2 + 1] * alpha;
                if (BIAS_MODE == 1) { v0 += bm; v1 += bm; }
                if (BIAS_MODE == 2) { v0 += bias[n]; v1 += bias[n + 1]; }
                size_t off = strideC * bz + (size_t)m * ldc + n;
                if (RES) {
                    float2 r2 = *(const float2*)&res[off];
                    v0 += r2.x; v1 += r2.y;
                }
                if (OHALF) {
                    *(__half2*)((__half*)Cout + off) = __floats2half2_rn(v0, v1);
                } else {
                    *(float2*)((float*)Cout + off) = make_float2(v0, v1);
                }
            }
        }
    }
}

// ---------------------------------------------------------------------------
// fp16 tensor-core 3-tap conv (implicit GEMM), cp.async 2-stage pipelined.
// Raw fp16 rows [16][144] + fp16 weight tiles double-buffered; patch built
// from smem under the MMA shadow. 2 CTAs/SM forced.
// M=C (co), N=L(128-tile), K=768 in 16 chunks of 48 (16 ci x 3 taps).
// ---------------------------------------------------------------------------
constexpr int CONV_SMEM = (2 * 128 * 56 + 2 * 16 * 144 + 128 * 56) * 2;  // 52224 B

template <bool ADDV, bool RES>
__global__ __launch_bounds__(256, 2) void conv_f16(
    const __half* __restrict__ in,   // [B][C][L] fp16
    const __half* __restrict__ w,    // [C][768]  fp16
    const float* __restrict__ bias,
    const float* __restrict__ addv,
    const float* __restrict__ resid,
    float* __restrict__ out)
{
    extern __shared__ __half hsmc[];
    __half (*sW)[128][56] = (__half(*)[128][56])hsmc;                // [stage]
    __half (*sR)[16][144] = (__half(*)[16][144])(hsmc + 2 * 128 * 56);
    __half (*sP)[56]      = (__half(*)[56])(hsmc + 2 * 128 * 56 + 2 * 16 * 144);

    int b  = blockIdx.z;
    int m0 = blockIdx.y * 128;
    int l0 = blockIdx.x * 128;
    int tid = threadIdx.x, lane = tid & 31, wid = tid >> 5;
    int wm = (wid & 3) * 32, wn = (wid >> 2) * 64;
    int g = lane >> 2, tg = lane & 3;

    auto issue_stage = [&](int kt, int stg) {
        int k0 = kt * 48, ci0 = kt * 16;
        #pragma unroll
        for (int it = 0; it < 3; it++) {
            int idx = tid + it * 256;
            int row = idx / 6, seg = (idx % 6) * 8;
            CP_ASYNC16(smem_u32(&sW[stg][row][seg]),
                       &w[(size_t)(m0 + row) * 768 + k0 + seg]);
        }
        for (int idx = tid; idx < 16 * 18; idx += 256) {
            int c = idx / 18, ch = (idx % 18) * 8;
            int l = l0 - 8 + ch;
            if (l >= 0 && l + 7 < L_) {
                CP_ASYNC16(smem_u32(&sR[stg][c][ch]),
                           &in[((size_t)(b * C_ + ci0 + c)) * L_ + l]);
            } else {
                *(uint4*)&sR[stg][c][ch] = make_uint4(0u, 0u, 0u, 0u);
            }
        }
    };

    float acc[2][8][4] = {};

    issue_stage(0, 0);
    CP_COMMIT();

    for (int kt = 0; kt < 16; kt++) {
        int st = kt & 1;
        CP_WAIT0();
        __syncthreads();

        // build patch [l][3*ci+t] from raw fp16 rows (LDS)
        for (int idx = tid; idx < 16 * 132; idx += 256) {
            int c = idx / 132, p = idx % 132;
            if (p < 130) {
                __half v = sR[st][c][p + 7];   // raw idx 7 <=> l = l0-1
                #pragma unroll
                for (int t_ = 0; t_ < 3; t_++) {
                    int j = p - t_;
                    if (j >= 0 && j < 128) sP[j][3 * c + t_] = v;
                }
            }
        }
        if (kt + 1 < 16) { issue_stage(kt + 1, st ^ 1); CP_COMMIT(); }
        __syncthreads();

        #pragma unroll
        for (int ks = 0; ks < 3; ks++) {
            int kb = ks * 16 + tg * 2;
            u32 afr[2][4], bfr[8][2];
            #pragma unroll
            for (int mt = 0; mt < 2; mt++) {
                int r = wm + mt * 16 + g;
                afr[mt][0] = *(const u32*)&sW[st][r][kb];
                afr[mt][1] = *(const u32*)&sW[st][r + 8][kb];
                afr[mt][2] = *(const u32*)&sW[st][r][kb + 8];
                afr[mt][3] = *(const u32*)&sW[st][r + 8][kb + 8];
            }
            #pragma unroll
            for (int nt = 0; nt < 8; nt++) {
                int c = wn + nt * 8 + g;
                bfr[nt][0] = *(const u32*)&sP[c][kb];
                bfr[nt][1] = *(const u32*)&sP[c][kb + 8];
            }
            #pragma unroll
            for (int mt = 0; mt < 2; mt++)
                #pragma unroll
                for (int nt = 0; nt < 8; nt++)
                    MMA_F16(acc[mt][nt], afr[mt], bfr[nt]);
        }
    }

    #pragma unroll
    for (int mt = 0; mt < 2; mt++) {
        #pragma unroll
        for (int half = 0; half < 2; half++) {
            int m = m0 + wm + mt * 16 + g + half * 8;
            float base = bias[m];
            if (ADDV) base += addv[b * C_ + m];
            #pragma unroll
            for (int nt = 0; nt < 8; nt++) {
                int n = l0 + wn + nt * 8 + tg * 2;
                float v0 = acc[mt][nt][half * 2 + 0] + base;
                float v1 = acc[mt][nt][half * 2 + 1] + base;
                size_t off = ((size_t)(b * C_ + m)) * L_ + n;
                if (RES) {
                    float2 r2 = *(const float2*)&resid[off];
                    v0 += r2.x; v1 += r2.y;
                }
                *(float2*)&out[off] = make_float2(v0, v1);
            }
        }
    }
}

// ---------------------------------------------------------------------------
// Row softmax — fp32 in, fp16 out. 2 rows per block, 128 thr/row, MLP 4.
// ---------------------------------------------------------------------------
__global__ __launch_bounds__(256) void softmax_kernel(const float* __restrict__ w,
                                                      __half* __restrict__ outp)
{
    __shared__ float red [2][4];
    __shared__ float red2[2][4];
    int tid  = threadIdx.x;
    int half_ = tid >> 7;
    int t    = tid & 127;
    int wh   = (tid >> 5) & 3;
    size_t row = (size_t)blockIdx.x * 2 + half_;
    const float4* p4 = (const float4*)(w + row * (size_t)L_);
    __half2* q2 = (__half2*)(outp + row * (size_t)L_);

    float4 va = p4[t], vb = p4[t + 128], vc = p4[t + 256], vd = p4[t + 384];
    float v[16] = { va.x, va.y, va.z, va.w, vb.x, vb.y, vb.z, vb.w,
                    vc.x, vc.y, vc.z, vc.w, vd.x, vd.y, vd.z, vd.w };

    float mx = v[0];
    #pragma unroll
    for (int i = 1; i < 16; i++) mx = fmaxf(mx, v[i]);
    #pragma unroll
    for (int o = 16; o > 0; o >>= 1) mx = fmaxf(mx, __shfl_xor_sync(0xffffffffu, mx, o));
    if ((tid & 31) == 0) red[half_][wh] = mx;
    __syncthreads();
    float m = fmaxf(fmaxf(red[half_][0], red[half_][1]),
                    fmaxf(red[half_][2], red[half_][3]));

    float s = 0.f;
    #pragma unroll
    for (int i = 0; i < 16; i++) { v[i] = __expf(v[i] - m); s += v[i]; }
    #pragma unroll
    for (int o = 16; o > 0; o >>= 1) s += __shfl_xor_sync(0xffffffffu, s, o);
    if ((tid & 31) == 0) red2[half_][wh] = s;
    __syncthreads();
    float inv = 1.f / (red2[half_][0] + red2[half_][1] + red2[half_][2] + red2[half_][3]);

    #pragma unroll
    for (int j = 0; j < 4; j++) {
        int base = 2 * (t + 128 * j);
        q2[base + 0] = __floats2half2_rn(v[4 * j + 0] * inv, v[4 * j + 1] * inv);
        q2[base + 1] = __floats2half2_rn(v[4 * j + 2] * inv, v[4 * j + 3] * inv);
    }
}

// ---------------------------------------------------------------------------
// Host orchestration (graph-capturable: kernel launches only)
// ---------------------------------------------------------------------------
extern "C" void kernel_launch(void* const* d_in, const int* in_sizes, int n_in,
                              void* d_out, int out_size)
{
    (void)in_sizes; (void)n_in; (void)out_size;

    const float* x   = (const float*)d_in[0];
    const int*   t   = (const int*)  d_in[1];
    const float* z0  = (const float*)d_in[2];
    const float* zt  = (const float*)d_in[3];
    const float* tw1 = (const float*)d_in[4];
    const float* tb1 = (const float*)d_in[5];
    const float* tw2 = (const float*)d_in[6];
    const float* tb2 = (const float*)d_in[7];
    const float* tpw = (const float*)d_in[8];
    const float* tpb = (const float*)d_in[9];
    const float* zpw = (const float*)d_in[10];
    const float* zpb = (const float*)d_in[11];
    const float* n1g = (const float*)d_in[12];
    const float* n1b = (const float*)d_in[13];
    const float* n2g = (const float*)d_in[14];
    const float* n2b = (const float*)d_in[15];
    const float* ng  = (const float*)d_in[16];
    const float* nb  = (const float*)d_in[17];
    const float* c1w = (const float*)d_in[18];
    const float* c1b = (const float*)d_in[19];
    const float* c2w = (const float*)d_in[20];
    const float* c2b = (const float*)d_in[21];
    const float* qw  = (const float*)d_in[22];
    const float* qb  = (const float*)d_in[23];
    const float* kw  = (const float*)d_in[24];
    const float* kb  = (const float*)d_in[25];
    const float* vw  = (const float*)d_in[26];
    const float* vb  = (const float*)d_in[27];
    const float* pw  = (const float*)d_in[28];
    const float* pb  = (const float*)d_in[29];
    float* out = (float*)d_out;

    __half *p_t1, *p_hnT, *p_qk, *p_v, *p_h2T, *p_wS, *p_wrh;
    float *p_h, *p_x1, *p_sc, *p_add, *p_bqk;
    float2* p_st;
    cudaGetSymbolAddress((void**)&p_t1,  g_t1);
    cudaGetSymbolAddress((void**)&p_h,   g_h);
    cudaGetSymbolAddress((void**)&p_x1,  g_x1);
    cudaGetSymbolAddress((void**)&p_hnT, g_hnT);
    cudaGetSymbolAddress((void**)&p_qk,  g_qk);
    cudaGetSymbolAddress((void**)&p_v,   g_v);
    cudaGetSymbolAddress((void**)&p_h2T, g_h2T);
    cudaGetSymbolAddress((void**)&p_sc,  g_sc);
    cudaGetSymbolAddress((void**)&p_wS,  g_wS);
    cudaGetSymbolAddress((void**)&p_add, g_add);
    cudaGetSymbolAddress((void**)&p_wrh, g_wrh);
    cudaGetSymbolAddress((void**)&p_bqk, g_bqk);
    cudaGetSymbolAddress((void**)&p_st,  g_st);

    __half* wr_qk  = p_wrh;                                  // [512][256]
    __half* wr_v   = p_wrh + 512 * C_;                       // [256][256]
    __half* wr_p   = wr_v + C_ * C_;                         // [256][256]
    __half* wr_c1  = wr_p + C_ * C_;                         // [256][768]
    __half* wr_c2  = wr_c1 + C_ * C_ * 3;                    // [256][768]

    // dynamic-smem attributes (host-side, idempotent)
    cudaFuncSetAttribute(gemm_f16<2, false, true>,
                         cudaFuncAttributeMaxDynamicSharedMemorySize, GEMM_SMEM);
    cudaFuncSetAttribute(gemm_f16<1, false, true>,
                         cudaFuncAttributeMaxDynamicSharedMemorySize, GEMM_SMEM);
    cudaFuncSetAttribute(gemm_f16<0, false, false>,
                         cudaFuncAttributeMaxDynamicSharedMemorySize, GEMM_SMEM);
    cudaFuncSetAttribute(gemm_f16<0, false, true>,
                         cudaFuncAttributeMaxDynamicSharedMemorySize, GEMM_SMEM);
    cudaFuncSetAttribute(gemm_f16<1, true, false>,
                         cudaFuncAttributeMaxDynamicSharedMemorySize, GEMM_SMEM);
    cudaFuncSetAttribute(conv_f16<true, false>,
                         cudaFuncAttributeMaxDynamicSharedMemorySize, CONV_SMEM);
    cudaFuncSetAttribute(conv_f16<false, true>,
                         cudaFuncAttributeMaxDynamicSharedMemorySize, CONV_SMEM);

    const size_t sCL  = (size_t)C_ * L_;    // [B,C,L] / [B,L,C] batch stride
    const size_t sQK  = (size_t)L_ * 512;   // [B,L,512] batch stride
    const size_t sLL  = (size_t)L_ * L_;    // [B,L,L] batch stride

    dim3 gconv(L_ / 128, C_ / 128, B_);

    // weight prep + temb
    round_f16_kernel<<<(C_ * C_ * 3 + 255) / 256, 256>>>(c1w, wr_c1, C_ * C_ * 3);
    round_f16_kernel<<<(C_ * C_ * 3 + 255) / 256, 256>>>(c2w, wr_c2, C_ * C_ * 3);
    temb_kernel<<<B_, 512>>>(t, z0, zt, tw1, tb1, tw2, tb2, tpw, tpb, zpw, zpb);
    concat_qk<<<(512 * C_ + 255) / 256, 256>>>(qw, kw, qb, kb, wr_qk, p_bqk);
    round_f16_kernel<<<(C_ * C_ + 255) / 256, 256>>>(vw, wr_v, C_ * C_);
    round_f16_kernel<<<(C_ * C_ + 255) / 256, 256>>>(pw, wr_p, C_ * C_);

    // stage 1: t1 = f16(silu(chan_norm(x, n1))); h = conv1(t1) + add
    norm_kernel<<<B_ * C_, 256>>>(x, p_t1, n1g, n1b);
    conv_f16<true, false><<<gconv, 256, CONV_SMEM>>>(p_t1, wr_c1, c1b,
                                                     p_add, nullptr, p_h);

    // stage 2: t1 = f16(silu(chan_norm(h, n2))); x1 = x + conv2(t1)
    norm_kernel<<<B_ * C_, 256>>>(p_h, p_t1, n2g, n2b);
    conv_f16<false, true><<<gconv, 256, CONV_SMEM>>>(p_t1, wr_c2, c2b,
                                                     nullptr, x, p_x1);

    // stage 3: stats(x1, n) -> fused norm+transpose -> hnT [B][L][C] f16
    stats_kernel<<<B_ * C_, 256>>>(p_x1, ng, nb, p_st);
    dim3 gtr(L_ / 32, C_ / 32, B_);
    transpose_norm<<<gtr, 256>>>(p_x1, p_st, p_hnT);

    // qk [L][512] = hnT @ [qw;kw]^T + b(per-n)    M=L, N=512, K=256
    dim3 gqk(512 / 128, L_ / 128, B_);
    gemm_f16<2, false, true><<<gqk, 256, GEMM_SMEM>>>(
        p_hnT, wr_qk, p_bqk, nullptr, p_qk,
        C_, C_, C_, 512, 1.f, sCL, 0, sQK);
    // v [C][L] = vw @ hn + b(per-m)               M=C, N=L, K=256
    dim3 gv(L_ / 128, C_ / 128, B_);
    gemm_f16<1, false, true><<<gv, 256, GEMM_SMEM>>>(
        wr_v, p_hnT, vb, nullptr, p_v,
        C_, C_, C_, L_, 1.f, 0, sCL, sCL);

    // scores[i][j] = (1/16) q[i]·k[j]             M=N=L, K=256 (ld 512), fp32 out
    dim3 gsc(L_ / 128, L_ / 128, B_);
    gemm_f16<0, false, false><<<gsc, 256, GEMM_SMEM>>>(
        p_qk, p_qk + 256, nullptr, nullptr, p_sc,
        C_, 512, 512, L_, 0.0625f, sQK, sQK, sLL);

    // softmax over j: fp32 scores -> fp16 weights
    softmax_kernel<<<B_ * L_ / 2, 256>>>(p_sc, p_wS);

    // h2T[i][c] = sum_j wS[i][j] v[c][j]          M=L, N=C, K=L
    dim3 gh2(C_ / 128, L_ / 128, B_);
    gemm_f16<0, false, true><<<gh2, 256, GEMM_SMEM>>>(
        p_wS, p_v, nullptr, nullptr, p_h2T,
        L_, L_, L_, C_, 1.f, sLL, sCL, sCL);

    // out[c][l] = pw @ h2 + pb + x1               M=C, N=L, K=256, fp32 out
    dim3 gpr(L_ / 128, C_ / 128, B_);
    gemm_f16<1, true, false><<<gpr, 256, GEMM_SMEM>>>(
        wr_p, p_h2T, pb, p_x1, out,
        C_, C_, C_, L_, 1.f, 0, sCL, sCL);
}

// round 14
// speedup vs baseline: 1.5562x; 1.1043x over previous
#include <cuda_runtime.h>
#include <cuda_fp16.h>
#include <math.h>
#include <stdint.h>

typedef unsigned int u32;

// ---------------------------------------------------------------------------
// Problem constants
// ---------------------------------------------------------------------------
constexpr int B_    = 16;
constexpr int C_    = 256;
constexpr int L_    = 2048;
constexpr int ZD_   = 128;
constexpr int TEMB_ = 512;
constexpr size_t BCL = (size_t)B_ * C_ * L_;
constexpr size_t BLL = (size_t)B_ * L_ * L_;

// ---------------------------------------------------------------------------
// Scratch (device globals; allocation-free per harness rules)
// ---------------------------------------------------------------------------
__device__ __align__(16) __half  g_t1 [BCL];                    // silu(norm(.)) fp16
__device__ __align__(16) float   g_h  [BCL];                    // conv1 output
__device__ __align__(16) float   g_x1 [BCL];                    // x + conv2(...)
__device__ __align__(16) __half  g_hnT[BCL];                    // norm(x1)^T [B][L][C]
__device__ __align__(16) __half  g_qk [(size_t)B_ * L_ * 512];  // q|k fused [B][L][512]
__device__ __align__(16) __half  g_v  [BCL];                    // v [B][C][L]
__device__ __align__(16) __half  g_h2T[BCL];                    // attn out [B][L][C]
__device__ __align__(16) __half  g_wS [BLL];                    // scores/softmax fp16
__device__ __align__(16) float   g_add[B_ * C_];                // temb/z projection
__device__ __align__(16) float2  g_st [B_ * C_];                // norm fold (fA, fB)
// fp16 weights: qk(512x256) | vw | pw | c1w | c2w
__device__ __align__(16) __half g_wrh[512 * C_ + 2 * C_ * C_ + 2 * C_ * C_ * 3];
__device__ __align__(16) float  g_bqk[512];                     // qb|kb bias

static __device__ __forceinline__ float silu_f(float x) {
    return x / (1.f + expf(-x));
}

#define MMA_F16(d, a, b)                                                      \
    asm volatile("mma.sync.aligned.m16n8k16.row.col.f32.f16.f16.f32 "         \
                 "{%0,%1,%2,%3},{%4,%5,%6,%7},{%8,%9},{%0,%1,%2,%3};"         \
                 : "+f"(d[0]), "+f"(d[1]), "+f"(d[2]), "+f"(d[3])             \
                 : "r"(a[0]), "r"(a[1]), "r"(a[2]), "r"(a[3]),                \
                   "r"(b[0]), "r"(b[1]))

#define CP_ASYNC16(dst_u32, src_ptr)                                          \
    asm volatile("cp.async.cg.shared.global [%0], [%1], 16;"                  \
                 :: "r"(dst_u32), "l"(src_ptr))
#define CP_COMMIT()  asm volatile("cp.async.commit_group;")
#define CP_WAIT0()   asm volatile("cp.async.wait_group 0;")
#define CP_WAIT1()   asm volatile("cp.async.wait_group 1;")

static __device__ __forceinline__ u32 smem_u32(const void* p) {
    return (u32)__cvta_generic_to_shared(p);
}

// ---------------------------------------------------------------------------
// Weight prep kernels (tiny, run once per launch)
// ---------------------------------------------------------------------------
__global__ void round_f16_kernel(const float* __restrict__ in,
                                 __half* __restrict__ out, int n)
{
    int i = blockIdx.x * 256 + threadIdx.x;
    if (i < n) out[i] = __float2half_rn(in[i]);
}

// concat qw|kw rows (512x256) + qb|kb (512), fp16 weights, fp32 bias
__global__ void concat_qk(const float* __restrict__ qw,
                          const float* __restrict__ kw,
                          const float* __restrict__ qb,
                          const float* __restrict__ kb,
                          __half* __restrict__ wdst,
                          float* __restrict__ bdst)
{
    int i = blockIdx.x * 256 + threadIdx.x;
    int total = 512 * C_;
    if (i < total) {
        int n = i >> 8;   // /256
        wdst[i] = __float2half_rn(n < C_ ? qw[i] : kw[i - C_ * C_]);
    }
    if (i < 512) bdst[i] = (i < C_) ? qb[i] : kb[i - C_];
}

// ---------------------------------------------------------------------------
// Kernel: timestep embedding MLP + fused add-vector (fp32, tiny)
// ---------------------------------------------------------------------------
__global__ void temb_kernel(const int* __restrict__ t,
                            const float* __restrict__ z0,
                            const float* __restrict__ zt,
                            const float* __restrict__ tw1, const float* __restrict__ tb1,
                            const float* __restrict__ tw2, const float* __restrict__ tb2,
                            const float* __restrict__ tpw, const float* __restrict__ tpb,
                            const float* __restrict__ zpw, const float* __restrict__ zpb)
{
    __shared__ float se[128];
    __shared__ float s1[512];
    __shared__ float s2[512];
    __shared__ float sz[256];

    int b = blockIdx.x, tid = threadIdx.x;

    if (tid < 64) {
        float f = expf((float)tid * (-logf(10000.f) / 63.f));
        float a = (float)t[b] * f;
        se[tid]      = sinf(a);
        se[64 + tid] = cosf(a);
    }
    if (tid < 128) {
        sz[tid]       = silu_f(z0[b * ZD_ + tid]);
        sz[128 + tid] = silu_f(zt[b * ZD_ + tid]);
    }
    __syncthreads();

    {
        float acc = tb1[tid];
        #pragma unroll 8
        for (int i = 0; i < 128; i++) acc += se[i] * tw1[i * TEMB_ + tid];
        s1[tid] = silu_f(acc);
    }
    __syncthreads();
    {
        float acc = tb2[tid];
        #pragma unroll 8
        for (int k = 0; k < 512; k++) acc += s1[k] * tw2[k * TEMB_ + tid];
        s2[tid] = silu_f(acc);
    }
    __syncthreads();

    if (tid < C_) {
        float acc = tpb[tid] + 2.f * zpb[tid];
        #pragma unroll 8
        for (int j = 0; j < 512; j++) acc += s2[j] * tpw[j * C_ + tid];
        #pragma unroll 8
        for (int i = 0; i < 128; i++) acc += (sz[i] + sz[128 + i]) * zpw[i * C_ + tid];
        g_add[b * C_ + tid] = acc;
    }
}

// ---------------------------------------------------------------------------
// Kernel: per-(b,c) channel norm over L, fused silu, fp16 output (conv input).
// ---------------------------------------------------------------------------
__global__ __launch_bounds__(256) void norm_kernel(const float* __restrict__ in,
                                                   __half* __restrict__ out,
                                                   const float* __restrict__ gam,
                                                   const float* __restrict__ bet)
{
    __shared__ float red[64];
    int row = blockIdx.x, tid = threadIdx.x;
    const float4* p4 = (const float4*)(in + (size_t)row * L_);

    float4 a = p4[tid];
    float4 b = p4[tid + 256];
    float v[8] = { a.x, a.y, a.z, a.w, b.x, b.y, b.z, b.w };
    float s = 0.f, sq = 0.f;
    #pragma unroll
    for (int i = 0; i < 8; i++) { s += v[i]; sq += v[i] * v[i]; }

    #pragma unroll
    for (int o = 16; o > 0; o >>= 1) {
        s  += __shfl_down_sync(0xffffffffu, s,  o);
        sq += __shfl_down_sync(0xffffffffu, sq, o);
    }
    if ((tid & 31) == 0) { red[tid >> 5] = s; red[8 + (tid >> 5)] = sq; }
    __syncthreads();
    if (tid < 32) {
        float aa = (tid < 8) ? red[tid]     : 0.f;
        float b2 = (tid < 8) ? red[8 + tid] : 0.f;
        #pragma unroll
        for (int o = 4; o > 0; o >>= 1) {
            aa += __shfl_down_sync(0xffffffffu, aa, o);
            b2 += __shfl_down_sync(0xffffffffu, b2, o);
        }
        if (tid == 0) { red[32] = aa; red[33] = b2; }
    }
    __syncthreads();

    float mean = red[32] * (1.f / L_);
    float var  = red[33] * (1.f / L_) - mean * mean;
    float rstd = rsqrtf(var + 1e-6f);
    int c = row & (C_ - 1);
    float gm = gam[c], bt = bet[c];

    float o8[8];
    #pragma unroll
    for (int i = 0; i < 8; i++) {
        float y = (v[i] - mean) * rstd * gm + bt;
        o8[i] = y / (1.f + expf(-y));
    }
    __half2* q2 = (__half2*)(out + (size_t)row * L_);
    q2[2 * tid + 0]       = __floats2half2_rn(o8[0], o8[1]);
    q2[2 * tid + 1]       = __floats2half2_rn(o8[2], o8[3]);
    q2[512 + 2 * tid + 0] = __floats2half2_rn(o8[4], o8[5]);
    q2[512 + 2 * tid + 1] = __floats2half2_rn(o8[6], o8[7]);
}

// ---------------------------------------------------------------------------
// Kernel: per-(b,c) norm statistics -> fold factors (fA, fB) for stage 3.
// ---------------------------------------------------------------------------
__global__ __launch_bounds__(256) void stats_kernel(const float* __restrict__ in,
                                                    const float* __restrict__ gam,
                                                    const float* __restrict__ bet,
                                                    float2* __restrict__ st)
{
    __shared__ float red[64];
    int row = blockIdx.x, tid = threadIdx.x;
    const float4* p4 = (const float4*)(in + (size_t)row * L_);

    float4 a = p4[tid];
    float4 b = p4[tid + 256];
    float s  = a.x + a.y + a.z + a.w + b.x + b.y + b.z + b.w;
    float sq = a.x * a.x + a.y * a.y + a.z * a.z + a.w * a.w
             + b.x * b.x + b.y * b.y + b.z * b.z + b.w * b.w;

    #pragma unroll
    for (int o = 16; o > 0; o >>= 1) {
        s  += __shfl_down_sync(0xffffffffu, s,  o);
        sq += __shfl_down_sync(0xffffffffu, sq, o);
    }
    if ((tid & 31) == 0) { red[tid >> 5] = s; red[8 + (tid >> 5)] = sq; }
    __syncthreads();
    if (tid == 0) {
        float S = 0.f, SQ = 0.f;
        #pragma unroll
        for (int i = 0; i < 8; i++) { S += red[i]; SQ += red[8 + i]; }
        float mean = S * (1.f / L_);
        float var  = SQ * (1.f / L_) - mean * mean;
        float rstd = rsqrtf(var + 1e-6f);
        int c = row & (C_ - 1);
        float fA = rstd * gam[c];
        st[row] = make_float2(fA, bet[c] - mean * fA);
    }
}

// ---------------------------------------------------------------------------
// Kernel: fused norm + 32x32 transpose, fp32 [B][C][L] -> fp16 [B][L][C].
// ---------------------------------------------------------------------------
__global__ __launch_bounds__(256) void transpose_norm(const float* __restrict__ in,
                                                      const float2* __restrict__ st,
                                                      __half* __restrict__ out)
{
    __shared__ float tile[32][33];
    int b = blockIdx.z;
    int l0 = blockIdx.x * 32, c0 = blockIdx.y * 32;
    int tx = threadIdx.x & 31, ty = threadIdx.x >> 5;
    #pragma unroll
    for (int i = 0; i < 4; i++) {
        int c = c0 + ty + i * 8;
        float2 f = st[b * C_ + c];
        float x = in[((size_t)(b * C_ + c)) * L_ + l0 + tx];
        tile[ty + i * 8][tx] = fmaf(x, f.x, f.y);
    }
    __syncthreads();
    #pragma unroll
    for (int i = 0; i < 4; i++) {
        int l = l0 + ty + i * 8;
        out[((size_t)b * L_ + l) * C_ + c0 + tx] = __float2half_rn(tile[tx][ty + i * 8]);
    }
}

// ---------------------------------------------------------------------------
// fp16 tensor-core GEMM (m16n8k16), cp.async 2-stage pipeline, k-tile 64,
// FORCED 2 CTAs/SM. Canonical NT: C[m][n] = alpha*sum_k A[m][k]*B[n][k].
// BIAS_MODE: 0 none, 1 per-m, 2 per-n. RES: fp32 residual. OHALF: out dtype.
// ---------------------------------------------------------------------------
constexpr int GEMM_SMEM = 2 * 2 * 128 * 72 * 2;   // 73728 B; x2 CTAs = 147 KB

template <int BIAS_MODE, bool RES, bool OHALF>
__global__ __launch_bounds__(256, 2) void gemm_f16(
    const __half* __restrict__ A, const __half* __restrict__ Bm,
    const float* __restrict__ bias, const float* __restrict__ res,
    void* __restrict__ Cout, int K, int lda, int ldb, int ldc,
    float alpha, size_t strideA, size_t strideB, size_t strideC)
{
    extern __shared__ __half hsm[];
    __half (*sA)[128][72] = (__half(*)[128][72])hsm;                 // [stage]
    __half (*sB)[128][72] = (__half(*)[128][72])(hsm + 2 * 128 * 72);

    int bz = blockIdx.z;
    A  += strideA * bz;
    Bm += strideB * bz;

    int m0 = blockIdx.y * 128, n0 = blockIdx.x * 128;
    int tid = threadIdx.x, lane = tid & 31, w = tid >> 5;
    int wm = (w & 3) * 32, wn = (w >> 2) * 64;
    int g = lane >> 2, tg = lane & 3;

    // copy coords: k-tile = 64 halves/row = 8 chunks of 8; 128 rows -> 1024 chunks
    int crow[4], cseg[4];
    #pragma unroll
    for (int it = 0; it < 4; it++) {
        int idx = tid + it * 256;
        crow[it] = idx >> 3;
        cseg[it] = (idx & 7) * 8;
    }

    float acc[2][8][4] = {};
    int KT = K / 64;

    auto issue = [&](int kt, int stg) {
        int kk = kt * 64;
        #pragma unroll
        for (int it = 0; it < 4; it++) {
            CP_ASYNC16(smem_u32(&sA[stg][crow[it]][cseg[it]]),
                       &A[(size_t)(m0 + crow[it]) * lda + kk + cseg[it]]);
            CP_ASYNC16(smem_u32(&sB[stg][crow[it]][cseg[it]]),
                       &Bm[(size_t)(n0 + crow[it]) * ldb + kk + cseg[it]]);
        }
    };

    issue(0, 0); CP_COMMIT();

    for (int kt = 0; kt < KT; kt++) {
        int st = kt & 1;
        if (kt + 1 < KT) { issue(kt + 1, st ^ 1); CP_COMMIT(); CP_WAIT1(); }
        else             { CP_WAIT0(); }
        __syncthreads();

        #pragma unroll
        for (int ks = 0; ks < 4; ks++) {
            int kb = ks * 16 + tg * 2;
            u32 afr[2][4], bfr[8][2];
            #pragma unroll
            for (int mt = 0; mt < 2; mt++) {
                int r = wm + mt * 16 + g;
                afr[mt][0] = *(const u32*)&sA[st][r][kb];
                afr[mt][1] = *(const u32*)&sA[st][r + 8][kb];
                afr[mt][2] = *(const u32*)&sA[st][r][kb + 8];
                afr[mt][3] = *(const u32*)&sA[st][r + 8][kb + 8];
            }
            #pragma unroll
            for (int nt = 0; nt < 8; nt++) {
                int c = wn + nt * 8 + g;
                bfr[nt][0] = *(const u32*)&sB[st][c][kb];
                bfr[nt][1] = *(const u32*)&sB[st][c][kb + 8];
            }
            #pragma unroll
            for (int mt = 0; mt < 2; mt++)
                #pragma unroll
                for (int nt = 0; nt < 8; nt++)
                    MMA_F16(acc[mt][nt], afr[mt], bfr[nt]);
        }
        __syncthreads();
    }

    // epilogue
    #pragma unroll
    for (int mt = 0; mt < 2; mt++) {
        #pragma unroll
        for (int half = 0; half < 2; half++) {
            int m = m0 + wm + mt * 16 + g + half * 8;
            float bm = (BIAS_MODE == 1) ? bias[m] : 0.f;
            #pragma unroll
            for (int nt = 0; nt < 8; nt++) {
                int n = n0 + wn + nt * 8 + tg * 2;
                float v0 = acc[mt][nt][half * 2 + 0] * alpha;
                float v1 = acc[mt][nt][half * 2 + 1] * alpha;
                if (BIAS_MODE == 1) { v0 += bm; v1 += bm; }
                if (BIAS_MODE == 2) { v0 += bias[n]; v1 += bias[n + 1]; }
                size_t off = strideC * bz + (size_t)m * ldc + n;
                if (RES) {
                    float2 r2 = *(const float2*)&res[off];
                    v0 += r2.x; v1 += r2.y;
                }
                if (OHALF) {
                    *(__half2*)((__half*)Cout + off) = __floats2half2_rn(v0, v1);
                } else {
                    *(float2*)((float*)Cout + off) = make_float2(v0, v1);
                }
            }
        }
    }
}

// ---------------------------------------------------------------------------
// fp16 tensor-core 3-tap conv (implicit GEMM), cp.async 2-stage pipelined.
// (unchanged from R13 WIN). 2 CTAs/SM forced.
// ---------------------------------------------------------------------------
constexpr int CONV_SMEM = (2 * 128 * 56 + 2 * 16 * 144 + 128 * 56) * 2;  // 52224 B

template <bool ADDV, bool RES>
__global__ __launch_bounds__(256, 2) void conv_f16(
    const __half* __restrict__ in,   // [B][C][L] fp16
    const __half* __restrict__ w,    // [C][768]  fp16
    const float* __restrict__ bias,
    const float* __restrict__ addv,
    const float* __restrict__ resid,
    float* __restrict__ out)
{
    extern __shared__ __half hsmc[];
    __half (*sW)[128][56] = (__half(*)[128][56])hsmc;                // [stage]
    __half (*sR)[16][144] = (__half(*)[16][144])(hsmc + 2 * 128 * 56);
    __half (*sP)[56]      = (__half(*)[56])(hsmc + 2 * 128 * 56 + 2 * 16 * 144);

    int b  = blockIdx.z;
    int m0 = blockIdx.y * 128;
    int l0 = blockIdx.x * 128;
    int tid = threadIdx.x, lane = tid & 31, wid = tid >> 5;
    int wm = (wid & 3) * 32, wn = (wid >> 2) * 64;
    int g = lane >> 2, tg = lane & 3;

    auto issue_stage = [&](int kt, int stg) {
        int k0 = kt * 48, ci0 = kt * 16;
        #pragma unroll
        for (int it = 0; it < 3; it++) {
            int idx = tid + it * 256;
            int row = idx / 6, seg = (idx % 6) * 8;
            CP_ASYNC16(smem_u32(&sW[stg][row][seg]),
                       &w[(size_t)(m0 + row) * 768 + k0 + seg]);
        }
        for (int idx = tid; idx < 16 * 18; idx += 256) {
            int c = idx / 18, ch = (idx % 18) * 8;
            int l = l0 - 8 + ch;
            if (l >= 0 && l + 7 < L_) {
                CP_ASYNC16(smem_u32(&sR[stg][c][ch]),
                           &in[((size_t)(b * C_ + ci0 + c)) * L_ + l]);
            } else {
                *(uint4*)&sR[stg][c][ch] = make_uint4(0u, 0u, 0u, 0u);
            }
        }
    };

    float acc[2][8][4] = {};

    issue_stage(0, 0);
    CP_COMMIT();

    for (int kt = 0; kt < 16; kt++) {
        int st = kt & 1;
        CP_WAIT0();
        __syncthreads();

        // build patch [l][3*ci+t] from raw fp16 rows (LDS)
        for (int idx = tid; idx < 16 * 132; idx += 256) {
            int c = idx / 132, p = idx % 132;
            if (p < 130) {
                __half v = sR[st][c][p + 7];   // raw idx 7 <=> l = l0-1
                #pragma unroll
                for (int t_ = 0; t_ < 3; t_++) {
                    int j = p - t_;
                    if (j >= 0 && j < 128) sP[j][3 * c + t_] = v;
                }
            }
        }
        if (kt + 1 < 16) { issue_stage(kt + 1, st ^ 1); CP_COMMIT(); }
        __syncthreads();

        #pragma unroll
        for (int ks = 0; ks < 3; ks++) {
            int kb = ks * 16 + tg * 2;
            u32 afr[2][4], bfr[8][2];
            #pragma unroll
            for (int mt = 0; mt < 2; mt++) {
                int r = wm + mt * 16 + g;
                afr[mt][0] = *(const u32*)&sW[st][r][kb];
                afr[mt][1] = *(const u32*)&sW[st][r + 8][kb];
                afr[mt][2] = *(const u32*)&sW[st][r][kb + 8];
                afr[mt][3] = *(const u32*)&sW[st][r + 8][kb + 8];
            }
            #pragma unroll
            for (int nt = 0; nt < 8; nt++) {
                int c = wn + nt * 8 + g;
                bfr[nt][0] = *(const u32*)&sP[c][kb];
                bfr[nt][1] = *(const u32*)&sP[c][kb + 8];
            }
            #pragma unroll
            for (int mt = 0; mt < 2; mt++)
                #pragma unroll
                for (int nt = 0; nt < 8; nt++)
                    MMA_F16(acc[mt][nt], afr[mt], bfr[nt]);
        }
    }

    #pragma unroll
    for (int mt = 0; mt < 2; mt++) {
        #pragma unroll
        for (int half = 0; half < 2; half++) {
            int m = m0 + wm + mt * 16 + g + half * 8;
            float base = bias[m];
            if (ADDV) base += addv[b * C_ + m];
            #pragma unroll
            for (int nt = 0; nt < 8; nt++) {
                int n = l0 + wn + nt * 8 + tg * 2;
                float v0 = acc[mt][nt][half * 2 + 0] + base;
                float v1 = acc[mt][nt][half * 2 + 1] + base;
                size_t off = ((size_t)(b * C_ + m)) * L_ + n;
                if (RES) {
                    float2 r2 = *(const float2*)&resid[off];
                    v0 += r2.x; v1 += r2.y;
                }
                *(float2*)&out[off] = make_float2(v0, v1);
            }
        }
    }
}

// ---------------------------------------------------------------------------
// Row softmax — fp16 in-place. 2 rows per block, 128 thr/row.
// Each thread: 16 halves via 2x uint4. Each block fully owns its rows.
// ---------------------------------------------------------------------------
__global__ __launch_bounds__(256) void softmax_kernel(__half* __restrict__ w)
{
    __shared__ float red [2][4];
    __shared__ float red2[2][4];
    int tid  = threadIdx.x;
    int half_ = tid >> 7;
    int t    = tid & 127;
    int wh   = (tid >> 5) & 3;
    size_t row = (size_t)blockIdx.x * 2 + half_;
    uint4* p4 = (uint4*)(w + row * (size_t)L_);   // 2048 halves = 256 uint4

    uint4 ua = p4[t], ub = p4[t + 128];
    float v[16];
    {
        const __half2* ha = (const __half2*)&ua;
        const __half2* hb = (const __half2*)&ub;
        #pragma unroll
        for (int i = 0; i < 4; i++) {
            float2 fa = __half22float2(ha[i]);
            float2 fb = __half22float2(hb[i]);
            v[2 * i + 0] = fa.x; v[2 * i + 1] = fa.y;
            v[8 + 2 * i + 0] = fb.x; v[8 + 2 * i + 1] = fb.y;
        }
    }

    float mx = v[0];
    #pragma unroll
    for (int i = 1; i < 16; i++) mx = fmaxf(mx, v[i]);
    #pragma unroll
    for (int o = 16; o > 0; o >>= 1) mx = fmaxf(mx, __shfl_xor_sync(0xffffffffu, mx, o));
    if ((tid & 31) == 0) red[half_][wh] = mx;
    __syncthreads();
    float m = fmaxf(fmaxf(red[half_][0], red[half_][1]),
                    fmaxf(red[half_][2], red[half_][3]));

    float s = 0.f;
    #pragma unroll
    for (int i = 0; i < 16; i++) { v[i] = __expf(v[i] - m); s += v[i]; }
    #pragma unroll
    for (int o = 16; o > 0; o >>= 1) s += __shfl_xor_sync(0xffffffffu, s, o);
    if ((tid & 31) == 0) red2[half_][wh] = s;
    __syncthreads();
    float inv = 1.f / (red2[half_][0] + red2[half_][1] + red2[half_][2] + red2[half_][3]);

    uint4 oa, ob;
    __half2* qa = (__half2*)&oa;
    __half2* qb = (__half2*)&ob;
    #pragma unroll
    for (int i = 0; i < 4; i++) {
        qa[i] = __floats2half2_rn(v[2 * i + 0] * inv, v[2 * i + 1] * inv);
        qb[i] = __floats2half2_rn(v[8 + 2 * i + 0] * inv, v[8 + 2 * i + 1] * inv);
    }
    p4[t]       = oa;
    p4[t + 128] = ob;
}

// ---------------------------------------------------------------------------
// Host orchestration (graph-capturable: kernel launches only)
// ---------------------------------------------------------------------------
extern "C" void kernel_launch(void* const* d_in, const int* in_sizes, int n_in,
                              void* d_out, int out_size)
{
    (void)in_sizes; (void)n_in; (void)out_size;

    const float* x   = (const float*)d_in[0];
    const int*   t   = (const int*)  d_in[1];
    const float* z0  = (const float*)d_in[2];
    const float* zt  = (const float*)d_in[3];
    const float* tw1 = (const float*)d_in[4];
    const float* tb1 = (const float*)d_in[5];
    const float* tw2 = (const float*)d_in[6];
    const float* tb2 = (const float*)d_in[7];
    const float* tpw = (const float*)d_in[8];
    const float* tpb = (const float*)d_in[9];
    const float* zpw = (const float*)d_in[10];
    const float* zpb = (const float*)d_in[11];
    const float* n1g = (const float*)d_in[12];
    const float* n1b = (const float*)d_in[13];
    const float* n2g = (const float*)d_in[14];
    const float* n2b = (const float*)d_in[15];
    const float* ng  = (const float*)d_in[16];
    const float* nb  = (const float*)d_in[17];
    const float* c1w = (const float*)d_in[18];
    const float* c1b = (const float*)d_in[19];
    const float* c2w = (const float*)d_in[20];
    const float* c2b = (const float*)d_in[21];
    const float* qw  = (const float*)d_in[22];
    const float* qb  = (const float*)d_in[23];
    const float* kw  = (const float*)d_in[24];
    const float* kb  = (const float*)d_in[25];
    const float* vw  = (const float*)d_in[26];
    const float* vb  = (const float*)d_in[27];
    const float* pw  = (const float*)d_in[28];
    const float* pb  = (const float*)d_in[29];
    float* out = (float*)d_out;

    __half *p_t1, *p_hnT, *p_qk, *p_v, *p_h2T, *p_wS, *p_wrh;
    float *p_h, *p_x1, *p_add, *p_bqk;
    float2* p_st;
    cudaGetSymbolAddress((void**)&p_t1,  g_t1);
    cudaGetSymbolAddress((void**)&p_h,   g_h);
    cudaGetSymbolAddress((void**)&p_x1,  g_x1);
    cudaGetSymbolAddress((void**)&p_hnT, g_hnT);
    cudaGetSymbolAddress((void**)&p_qk,  g_qk);
    cudaGetSymbolAddress((void**)&p_v,   g_v);
    cudaGetSymbolAddress((void**)&p_h2T, g_h2T);
    cudaGetSymbolAddress((void**)&p_wS,  g_wS);
    cudaGetSymbolAddress((void**)&p_add, g_add);
    cudaGetSymbolAddress((void**)&p_wrh, g_wrh);
    cudaGetSymbolAddress((void**)&p_bqk, g_bqk);
    cudaGetSymbolAddress((void**)&p_st,  g_st);

    __half* wr_qk  = p_wrh;                                  // [512][256]
    __half* wr_v   = p_wrh + 512 * C_;                       // [256][256]
    __half* wr_p   = wr_v + C_ * C_;                         // [256][256]
    __half* wr_c1  = wr_p + C_ * C_;                         // [256][768]
    __half* wr_c2  = wr_c1 + C_ * C_ * 3;                    // [256][768]

    // dynamic-smem attributes (host-side, idempotent)
    cudaFuncSetAttribute(gemm_f16<2, false, true>,
                         cudaFuncAttributeMaxDynamicSharedMemorySize, GEMM_SMEM);
    cudaFuncSetAttribute(gemm_f16<1, false, true>,
                         cudaFuncAttributeMaxDynamicSharedMemorySize, GEMM_SMEM);
    cudaFuncSetAttribute(gemm_f16<0, false, true>,
                         cudaFuncAttributeMaxDynamicSharedMemorySize, GEMM_SMEM);
    cudaFuncSetAttribute(gemm_f16<1, true, false>,
                         cudaFuncAttributeMaxDynamicSharedMemorySize, GEMM_SMEM);
    cudaFuncSetAttribute(conv_f16<true, false>,
                         cudaFuncAttributeMaxDynamicSharedMemorySize, CONV_SMEM);
    cudaFuncSetAttribute(conv_f16<false, true>,
                         cudaFuncAttributeMaxDynamicSharedMemorySize, CONV_SMEM);

    const size_t sCL  = (size_t)C_ * L_;    // [B,C,L] / [B,L,C] batch stride
    const size_t sQK  = (size_t)L_ * 512;   // [B,L,512] batch stride
    const size_t sLL  = (size_t)L_ * L_;    // [B,L,L] batch stride

    dim3 gconv(L_ / 128, C_ / 128, B_);

    // weight prep + temb
    round_f16_kernel<<<(C_ * C_ * 3 + 255) / 256, 256>>>(c1w, wr_c1, C_ * C_ * 3);
    round_f16_kernel<<<(C_ * C_ * 3 + 255) / 256, 256>>>(c2w, wr_c2, C_ * C_ * 3);
    temb_kernel<<<B_, 512>>>(t, z0, zt, tw1, tb1, tw2, tb2, tpw, tpb, zpw, zpb);
    concat_qk<<<(512 * C_ + 255) / 256, 256>>>(qw, kw, qb, kb, wr_qk, p_bqk);
    round_f16_kernel<<<(C_ * C_ + 255) / 256, 256>>>(vw, wr_v, C_ * C_);
    round_f16_kernel<<<(C_ * C_ + 255) / 256, 256>>>(pw, wr_p, C_ * C_);

    // stage 1: t1 = f16(silu(chan_norm(x, n1))); h = conv1(t1) + add
    norm_kernel<<<B_ * C_, 256>>>(x, p_t1, n1g, n1b);
    conv_f16<true, false><<<gconv, 256, CONV_SMEM>>>(p_t1, wr_c1, c1b,
                                                     p_add, nullptr, p_h);

    // stage 2: t1 = f16(silu(chan_norm(h, n2))); x1 = x + conv2(t1)
    norm_kernel<<<B_ * C_, 256>>>(p_h, p_t1, n2g, n2b);
    conv_f16<false, true><<<gconv, 256, CONV_SMEM>>>(p_t1, wr_c2, c2b,
                                                     nullptr, x, p_x1);

    // stage 3: stats(x1, n) -> fused norm+transpose -> hnT [B][L][C] f16
    stats_kernel<<<B_ * C_, 256>>>(p_x1, ng, nb, p_st);
    dim3 gtr(L_ / 32, C_ / 32, B_);
    transpose_norm<<<gtr, 256>>>(p_x1, p_st, p_hnT);

    // qk [L][512] = hnT @ [qw;kw]^T + b(per-n)    M=L, N=512, K=256
    dim3 gqk(512 / 128, L_ / 128, B_);
    gemm_f16<2, false, true><<<gqk, 256, GEMM_SMEM>>>(
        p_hnT, wr_qk, p_bqk, nullptr, p_qk,
        C_, C_, C_, 512, 1.f, sCL, 0, sQK);
    // v [C][L] = vw @ hn + b(per-m)               M=C, N=L, K=256
    dim3 gv(L_ / 128, C_ / 128, B_);
    gemm_f16<1, false, true><<<gv, 256, GEMM_SMEM>>>(
        wr_v, p_hnT, vb, nullptr, p_v,
        C_, C_, C_, L_, 1.f, 0, sCL, sCL);

    // scores[i][j] = (1/16) q[i]·k[j] -> fp16     M=N=L, K=256 (ld 512)
    dim3 gsc(L_ / 128, L_ / 128, B_);
    gemm_f16<0, false, true><<<gsc, 256, GEMM_SMEM>>>(
        p_qk, p_qk + 256, nullptr, nullptr, p_wS,
        C_, 512, 512, L_, 0.0625f, sQK, sQK, sLL);

    // softmax over j: fp16 in-place
    softmax_kernel<<<B_ * L_ / 2, 256>>>(p_wS);

    // h2T[i][c] = sum_j wS[i][j] v[c][j]          M=L, N=C, K=L
    dim3 gh2(C_ / 128, L_ / 128, B_);
    gemm_f16<0, false, true><<<gh2, 256, GEMM_SMEM>>>(
        p_wS, p_v, nullptr, nullptr, p_h2T,
        L_, L_, L_, C_, 1.f, sLL, sCL, sCL);

    // out[c][l] = pw @ h2 + pb + x1               M=C, N=L, K=256, fp32 out
    dim3 gpr(L_ / 128, C_ / 128, B_);
    gemm_f16<1, true, false><<<gpr, 256, GEMM_SMEM>>>(
        wr_p, p_h2T, pb, p_x1, out,
        C_, C_, C_, L_, 1.f, 0, sCL, sCL);
}

// round 15
// speedup vs baseline: 1.5704x; 1.0091x over previous
#include <cuda_runtime.h>
#include <cuda_fp16.h>
#include <math.h>
#include <stdint.h>

typedef unsigned int u32;

// ---------------------------------------------------------------------------
// Problem constants
// ---------------------------------------------------------------------------
constexpr int B_    = 16;
constexpr int C_    = 256;
constexpr int L_    = 2048;
constexpr int ZD_   = 128;
constexpr int TEMB_ = 512;
constexpr size_t BCL = (size_t)B_ * C_ * L_;
constexpr size_t BLL = (size_t)B_ * L_ * L_;

// ---------------------------------------------------------------------------
// Scratch (device globals; allocation-free per harness rules)
// ---------------------------------------------------------------------------
__device__ __align__(16) __half  g_t1 [BCL];                    // silu(norm(.)) fp16
__device__ __align__(16) float   g_h  [BCL];                    // conv1 output
__device__ __align__(16) float   g_x1 [BCL];                    // x + conv2(...)
__device__ __align__(16) __half  g_hnT[BCL];                    // norm(x1)^T [B][L][C]
__device__ __align__(16) __half  g_qk [(size_t)B_ * L_ * 512];  // q|k fused [B][L][512]
__device__ __align__(16) __half  g_v  [BCL];                    // v [B][C][L]
__device__ __align__(16) __half  g_h2T[BCL];                    // attn out [B][L][C]
__device__ __align__(16) __half  g_wS [BLL];                    // scores/softmax fp16
__device__ __align__(16) float   g_add[B_ * C_];                // temb/z projection
__device__ __align__(16) float2  g_st [B_ * C_];                // norm fold (fA, fB)
// fp16 weights: qk(512x256) | vw | pw | c1w | c2w
__device__ __align__(16) __half g_wrh[512 * C_ + 2 * C_ * C_ + 2 * C_ * C_ * 3];
__device__ __align__(16) float  g_bqk[512];                     // qb|kb bias

static __device__ __forceinline__ float silu_f(float x) {
    return x / (1.f + expf(-x));
}

#define MMA_F16(d, a, b)                                                      \
    asm volatile("mma.sync.aligned.m16n8k16.row.col.f32.f16.f16.f32 "         \
                 "{%0,%1,%2,%3},{%4,%5,%6,%7},{%8,%9},{%0,%1,%2,%3};"         \
                 : "+f"(d[0]), "+f"(d[1]), "+f"(d[2]), "+f"(d[3])             \
                 : "r"(a[0]), "r"(a[1]), "r"(a[2]), "r"(a[3]),                \
                   "r"(b[0]), "r"(b[1]))

#define CP_ASYNC16(dst_u32, src_ptr)                                          \
    asm volatile("cp.async.cg.shared.global [%0], [%1], 16;"                  \
                 :: "r"(dst_u32), "l"(src_ptr))
#define CP_COMMIT()  asm volatile("cp.async.commit_group;")
#define CP_WAIT0()   asm volatile("cp.async.wait_group 0;")
#define CP_WAIT1()   asm volatile("cp.async.wait_group 1;")

static __device__ __forceinline__ u32 smem_u32(const void* p) {
    return (u32)__cvta_generic_to_shared(p);
}

// ---------------------------------------------------------------------------
// Weight prep kernels (tiny, run once per launch)
// ---------------------------------------------------------------------------
__global__ void round_f16_kernel(const float* __restrict__ in,
                                 __half* __restrict__ out, int n)
{
    int i = blockIdx.x * 256 + threadIdx.x;
    if (i < n) out[i] = __float2half_rn(in[i]);
}

// concat qw|kw rows (512x256) + qb|kb (512), fp16 weights, fp32 bias
__global__ void concat_qk(const float* __restrict__ qw,
                          const float* __restrict__ kw,
                          const float* __restrict__ qb,
                          const float* __restrict__ kb,
                          __half* __restrict__ wdst,
                          float* __restrict__ bdst)
{
    int i = blockIdx.x * 256 + threadIdx.x;
    int total = 512 * C_;
    if (i < total) {
        int n = i >> 8;   // /256
        wdst[i] = __float2half_rn(n < C_ ? qw[i] : kw[i - C_ * C_]);
    }
    if (i < 512) bdst[i] = (i < C_) ? qb[i] : kb[i - C_];
}

// ---------------------------------------------------------------------------
// Kernel: timestep embedding MLP + fused add-vector (fp32, tiny)
// ---------------------------------------------------------------------------
__global__ void temb_kernel(const int* __restrict__ t,
                            const float* __restrict__ z0,
                            const float* __restrict__ zt,
                            const float* __restrict__ tw1, const float* __restrict__ tb1,
                            const float* __restrict__ tw2, const float* __restrict__ tb2,
                            const float* __restrict__ tpw, const float* __restrict__ tpb,
                            const float* __restrict__ zpw, const float* __restrict__ zpb)
{
    __shared__ float se[128];
    __shared__ float s1[512];
    __shared__ float s2[512];
    __shared__ float sz[256];

    int b = blockIdx.x, tid = threadIdx.x;

    if (tid < 64) {
        float f = expf((float)tid * (-logf(10000.f) / 63.f));
        float a = (float)t[b] * f;
        se[tid]      = sinf(a);
        se[64 + tid] = cosf(a);
    }
    if (tid < 128) {
        sz[tid]       = silu_f(z0[b * ZD_ + tid]);
        sz[128 + tid] = silu_f(zt[b * ZD_ + tid]);
    }
    __syncthreads();

    {
        float acc = tb1[tid];
        #pragma unroll 8
        for (int i = 0; i < 128; i++) acc += se[i] * tw1[i * TEMB_ + tid];
        s1[tid] = silu_f(acc);
    }
    __syncthreads();
    {
        float acc = tb2[tid];
        #pragma unroll 8
        for (int k = 0; k < 512; k++) acc += s1[k] * tw2[k * TEMB_ + tid];
        s2[tid] = silu_f(acc);
    }
    __syncthreads();

    if (tid < C_) {
        float acc = tpb[tid] + 2.f * zpb[tid];
        #pragma unroll 8
        for (int j = 0; j < 512; j++) acc += s2[j] * tpw[j * C_ + tid];
        #pragma unroll 8
        for (int i = 0; i < 128; i++) acc += (sz[i] + sz[128 + i]) * zpw[i * C_ + tid];
        g_add[b * C_ + tid] = acc;
    }
}

// ---------------------------------------------------------------------------
// Kernel: per-(b,c) channel norm over L, fused silu, fp16 output (conv input).
// ---------------------------------------------------------------------------
__global__ __launch_bounds__(256) void norm_kernel(const float* __restrict__ in,
                                                   __half* __restrict__ out,
                                                   const float* __restrict__ gam,
                                                   const float* __restrict__ bet)
{
    __shared__ float red[64];
    int row = blockIdx.x, tid = threadIdx.x;
    const float4* p4 = (const float4*)(in + (size_t)row * L_);

    float4 a = p4[tid];
    float4 b = p4[tid + 256];
    float v[8] = { a.x, a.y, a.z, a.w, b.x, b.y, b.z, b.w };
    float s = 0.f, sq = 0.f;
    #pragma unroll
    for (int i = 0; i < 8; i++) { s += v[i]; sq += v[i] * v[i]; }

    #pragma unroll
    for (int o = 16; o > 0; o >>= 1) {
        s  += __shfl_down_sync(0xffffffffu, s,  o);
        sq += __shfl_down_sync(0xffffffffu, sq, o);
    }
    if ((tid & 31) == 0) { red[tid >> 5] = s; red[8 + (tid >> 5)] = sq; }
    __syncthreads();
    if (tid < 32) {
        float aa = (tid < 8) ? red[tid]     : 0.f;
        float b2 = (tid < 8) ? red[8 + tid] : 0.f;
        #pragma unroll
        for (int o = 4; o > 0; o >>= 1) {
            aa += __shfl_down_sync(0xffffffffu, aa, o);
            b2 += __shfl_down_sync(0xffffffffu, b2, o);
        }
        if (tid == 0) { red[32] = aa; red[33] = b2; }
    }
    __syncthreads();

    float mean = red[32] * (1.f / L_);
    float var  = red[33] * (1.f / L_) - mean * mean;
    float rstd = rsqrtf(var + 1e-6f);
    int c = row & (C_ - 1);
    float gm = gam[c], bt = bet[c];

    float o8[8];
    #pragma unroll
    for (int i = 0; i < 8; i++) {
        float y = (v[i] - mean) * rstd * gm + bt;
        o8[i] = y / (1.f + expf(-y));
    }
    __half2* q2 = (__half2*)(out + (size_t)row * L_);
    q2[2 * tid + 0]       = __floats2half2_rn(o8[0], o8[1]);
    q2[2 * tid + 1]       = __floats2half2_rn(o8[2], o8[3]);
    q2[512 + 2 * tid + 0] = __floats2half2_rn(o8[4], o8[5]);
    q2[512 + 2 * tid + 1] = __floats2half2_rn(o8[6], o8[7]);
}

// ---------------------------------------------------------------------------
// Kernel: per-(b,c) norm statistics -> fold factors (fA, fB) for stage 3.
// ---------------------------------------------------------------------------
__global__ __launch_bounds__(256) void stats_kernel(const float* __restrict__ in,
                                                    const float* __restrict__ gam,
                                                    const float* __restrict__ bet,
                                                    float2* __restrict__ st)
{
    __shared__ float red[64];
    int row = blockIdx.x, tid = threadIdx.x;
    const float4* p4 = (const float4*)(in + (size_t)row * L_);

    float4 a = p4[tid];
    float4 b = p4[tid + 256];
    float s  = a.x + a.y + a.z + a.w + b.x + b.y + b.z + b.w;
    float sq = a.x * a.x + a.y * a.y + a.z * a.z + a.w * a.w
             + b.x * b.x + b.y * b.y + b.z * b.z + b.w * b.w;

    #pragma unroll
    for (int o = 16; o > 0; o >>= 1) {
        s  += __shfl_down_sync(0xffffffffu, s,  o);
        sq += __shfl_down_sync(0xffffffffu, sq, o);
    }
    if ((tid & 31) == 0) { red[tid >> 5] = s; red[8 + (tid >> 5)] = sq; }
    __syncthreads();
    if (tid == 0) {
        float S = 0.f, SQ = 0.f;
        #pragma unroll
        for (int i = 0; i < 8; i++) { S += red[i]; SQ += red[8 + i]; }
        float mean = S * (1.f / L_);
        float var  = SQ * (1.f / L_) - mean * mean;
        float rstd = rsqrtf(var + 1e-6f);
        int c = row & (C_ - 1);
        float fA = rstd * gam[c];
        st[row] = make_float2(fA, bet[c] - mean * fA);
    }
}

// ---------------------------------------------------------------------------
// Kernel: fused norm + 32x32 transpose, fp32 [B][C][L] -> fp16 [B][L][C].
// ---------------------------------------------------------------------------
__global__ __launch_bounds__(256) void transpose_norm(const float* __restrict__ in,
                                                      const float2* __restrict__ st,
                                                      __half* __restrict__ out)
{
    __shared__ float tile[32][33];
    int b = blockIdx.z;
    int l0 = blockIdx.x * 32, c0 = blockIdx.y * 32;
    int tx = threadIdx.x & 31, ty = threadIdx.x >> 5;
    #pragma unroll
    for (int i = 0; i < 4; i++) {
        int c = c0 + ty + i * 8;
        float2 f = st[b * C_ + c];
        float x = in[((size_t)(b * C_ + c)) * L_ + l0 + tx];
        tile[ty + i * 8][tx] = fmaf(x, f.x, f.y);
    }
    __syncthreads();
    #pragma unroll
    for (int i = 0; i < 4; i++) {
        int l = l0 + ty + i * 8;
        out[((size_t)b * L_ + l) * C_ + c0 + tx] = __float2half_rn(tile[tx][ty + i * 8]);
    }
}

// ---------------------------------------------------------------------------
// fp16 tensor-core GEMM (m16n8k16), cp.async 2-stage pipeline, k-tile 64,
// FORCED 2 CTAs/SM. (unchanged from R14 WIN)
// ---------------------------------------------------------------------------
constexpr int GEMM_SMEM = 2 * 2 * 128 * 72 * 2;   // 73728 B; x2 CTAs = 147 KB

template <int BIAS_MODE, bool RES, bool OHALF>
__global__ __launch_bounds__(256, 2) void gemm_f16(
    const __half* __restrict__ A, const __half* __restrict__ Bm,
    const float* __restrict__ bias, const float* __restrict__ res,
    void* __restrict__ Cout, int K, int lda, int ldb, int ldc,
    float alpha, size_t strideA, size_t strideB, size_t strideC)
{
    extern __shared__ __half hsm[];
    __half (*sA)[128][72] = (__half(*)[128][72])hsm;                 // [stage]
    __half (*sB)[128][72] = (__half(*)[128][72])(hsm + 2 * 128 * 72);

    int bz = blockIdx.z;
    A  += strideA * bz;
    Bm += strideB * bz;

    int m0 = blockIdx.y * 128, n0 = blockIdx.x * 128;
    int tid = threadIdx.x, lane = tid & 31, w = tid >> 5;
    int wm = (w & 3) * 32, wn = (w >> 2) * 64;
    int g = lane >> 2, tg = lane & 3;

    int crow[4], cseg[4];
    #pragma unroll
    for (int it = 0; it < 4; it++) {
        int idx = tid + it * 256;
        crow[it] = idx >> 3;
        cseg[it] = (idx & 7) * 8;
    }

    float acc[2][8][4] = {};
    int KT = K / 64;

    auto issue = [&](int kt, int stg) {
        int kk = kt * 64;
        #pragma unroll
        for (int it = 0; it < 4; it++) {
            CP_ASYNC16(smem_u32(&sA[stg][crow[it]][cseg[it]]),
                       &A[(size_t)(m0 + crow[it]) * lda + kk + cseg[it]]);
            CP_ASYNC16(smem_u32(&sB[stg][crow[it]][cseg[it]]),
                       &Bm[(size_t)(n0 + crow[it]) * ldb + kk + cseg[it]]);
        }
    };

    issue(0, 0); CP_COMMIT();

    for (int kt = 0; kt < KT; kt++) {
        int st = kt & 1;
        if (kt + 1 < KT) { issue(kt + 1, st ^ 1); CP_COMMIT(); CP_WAIT1(); }
        else             { CP_WAIT0(); }
        __syncthreads();

        #pragma unroll
        for (int ks = 0; ks < 4; ks++) {
            int kb = ks * 16 + tg * 2;
            u32 afr[2][4], bfr[8][2];
            #pragma unroll
            for (int mt = 0; mt < 2; mt++) {
                int r = wm + mt * 16 + g;
                afr[mt][0] = *(const u32*)&sA[st][r][kb];
                afr[mt][1] = *(const u32*)&sA[st][r + 8][kb];
                afr[mt][2] = *(const u32*)&sA[st][r][kb + 8];
                afr[mt][3] = *(const u32*)&sA[st][r + 8][kb + 8];
            }
            #pragma unroll
            for (int nt = 0; nt < 8; nt++) {
                int c = wn + nt * 8 + g;
                bfr[nt][0] = *(const u32*)&sB[st][c][kb];
                bfr[nt][1] = *(const u32*)&sB[st][c][kb + 8];
            }
            #pragma unroll
            for (int mt = 0; mt < 2; mt++)
                #pragma unroll
                for (int nt = 0; nt < 8; nt++)
                    MMA_F16(acc[mt][nt], afr[mt], bfr[nt]);
        }
        __syncthreads();
    }

    // epilogue
    #pragma unroll
    for (int mt = 0; mt < 2; mt++) {
        #pragma unroll
        for (int half = 0; half < 2; half++) {
            int m = m0 + wm + mt * 16 + g + half * 8;
            float bm = (BIAS_MODE == 1) ? bias[m] : 0.f;
            #pragma unroll
            for (int nt = 0; nt < 8; nt++) {
                int n = n0 + wn + nt * 8 + tg * 2;
                float v0 = acc[mt][nt][half * 2 + 0] * alpha;
                float v1 = acc[mt][nt][half * 2 + 1] * alpha;
                if (BIAS_MODE == 1) { v0 += bm; v1 += bm; }
                if (BIAS_MODE == 2) { v0 += bias[n]; v1 += bias[n + 1]; }
                size_t off = strideC * bz + (size_t)m * ldc + n;
                if (RES) {
                    float2 r2 = *(const float2*)&res[off];
                    v0 += r2.x; v1 += r2.y;
                }
                if (OHALF) {
                    *(__half2*)((__half*)Cout + off) = __floats2half2_rn(v0, v1);
                } else {
                    *(float2*)((float*)Cout + off) = make_float2(v0, v1);
                }
            }
        }
    }
}

// ---------------------------------------------------------------------------
// fp16 tensor-core 3-tap conv (implicit GEMM), cp.async 2-stage pipelined.
// k-chunk 96 (32 ci x 3 taps), 8 chunks — half the syncs of the 48-chunk
// version; identical (ci,tap) MMA sequence (bit-identical math).
// smem: 2*128*104 (W) + 2*32*144 (raw) + 128*104 (patch) halves = 96 KB.
// ---------------------------------------------------------------------------
constexpr int CONV_SMEM = (2 * 128 * 104 + 2 * 32 * 144 + 128 * 104) * 2;

template <bool ADDV, bool RES>
__global__ __launch_bounds__(256, 2) void conv_f16(
    const __half* __restrict__ in,   // [B][C][L] fp16
    const __half* __restrict__ w,    // [C][768]  fp16
    const float* __restrict__ bias,
    const float* __restrict__ addv,
    const float* __restrict__ resid,
    float* __restrict__ out)
{
    extern __shared__ __half hsmc[];
    __half (*sW)[128][104] = (__half(*)[128][104])hsmc;              // [stage]
    __half (*sR)[32][144]  = (__half(*)[32][144])(hsmc + 2 * 128 * 104);
    __half (*sP)[104]      = (__half(*)[104])(hsmc + 2 * 128 * 104 + 2 * 32 * 144);

    int b  = blockIdx.z;
    int m0 = blockIdx.y * 128;
    int l0 = blockIdx.x * 128;
    int tid = threadIdx.x, lane = tid & 31, wid = tid >> 5;
    int wm = (wid & 3) * 32, wn = (wid >> 2) * 64;
    int g = lane >> 2, tg = lane & 3;

    auto issue_stage = [&](int kt, int stg) {
        int k0 = kt * 96, ci0 = kt * 32;
        #pragma unroll
        for (int it = 0; it < 6; it++) {
            int idx = tid + it * 256;
            int row = idx / 12, seg = (idx % 12) * 8;
            CP_ASYNC16(smem_u32(&sW[stg][row][seg]),
                       &w[(size_t)(m0 + row) * 768 + k0 + seg]);
        }
        for (int idx = tid; idx < 32 * 18; idx += 256) {
            int c = idx / 18, ch = (idx % 18) * 8;
            int l = l0 - 8 + ch;
            if (l >= 0 && l + 7 < L_) {
                CP_ASYNC16(smem_u32(&sR[stg][c][ch]),
                           &in[((size_t)(b * C_ + ci0 + c)) * L_ + l]);
            } else {
                *(uint4*)&sR[stg][c][ch] = make_uint4(0u, 0u, 0u, 0u);
            }
        }
    };

    float acc[2][8][4] = {};

    issue_stage(0, 0);
    CP_COMMIT();

    for (int kt = 0; kt < 8; kt++) {
        int st = kt & 1;
        CP_WAIT0();
        __syncthreads();

        // build patch [l][3*ci+t] from raw fp16 rows (LDS)
        for (int idx = tid; idx < 32 * 132; idx += 256) {
            int c = idx / 132, p = idx % 132;
            if (p < 130) {
                __half v = sR[st][c][p + 7];   // raw idx 7 <=> l = l0-1
                #pragma unroll
                for (int t_ = 0; t_ < 3; t_++) {
                    int j = p - t_;
                    if (j >= 0 && j < 128) sP[j][3 * c + t_] = v;
                }
            }
        }
        if (kt + 1 < 8) { issue_stage(kt + 1, st ^ 1); CP_COMMIT(); }
        __syncthreads();

        #pragma unroll
        for (int ks = 0; ks < 6; ks++) {
            int kb = ks * 16 + tg * 2;
            u32 afr[2][4], bfr[8][2];
            #pragma unroll
            for (int mt = 0; mt < 2; mt++) {
                int r = wm + mt * 16 + g;
                afr[mt][0] = *(const u32*)&sW[st][r][kb];
                afr[mt][1] = *(const u32*)&sW[st][r + 8][kb];
                afr[mt][2] = *(const u32*)&sW[st][r][kb + 8];
                afr[mt][3] = *(const u32*)&sW[st][r + 8][kb + 8];
            }
            #pragma unroll
            for (int nt = 0; nt < 8; nt++) {
                int c = wn + nt * 8 + g;
                bfr[nt][0] = *(const u32*)&sP[c][kb];
                bfr[nt][1] = *(const u32*)&sP[c][kb + 8];
            }
            #pragma unroll
            for (int mt = 0; mt < 2; mt++)
                #pragma unroll
                for (int nt = 0; nt < 8; nt++)
                    MMA_F16(acc[mt][nt], afr[mt], bfr[nt]);
        }
    }

    #pragma unroll
    for (int mt = 0; mt < 2; mt++) {
        #pragma unroll
        for (int half = 0; half < 2; half++) {
            int m = m0 + wm + mt * 16 + g + half * 8;
            float base = bias[m];
            if (ADDV) base += addv[b * C_ + m];
            #pragma unroll
            for (int nt = 0; nt < 8; nt++) {
                int n = l0 + wn + nt * 8 + tg * 2;
                float v0 = acc[mt][nt][half * 2 + 0] + base;
                float v1 = acc[mt][nt][half * 2 + 1] + base;
                size_t off = ((size_t)(b * C_ + m)) * L_ + n;
                if (RES) {
                    float2 r2 = *(const float2*)&resid[off];
                    v0 += r2.x; v1 += r2.y;
                }
                *(float2*)&out[off] = make_float2(v0, v1);
            }
        }
    }
}

// ---------------------------------------------------------------------------
// Row softmax — fp16 in-place. 2 rows per block, 128 thr/row.
// ---------------------------------------------------------------------------
__global__ __launch_bounds__(256) void softmax_kernel(__half* __restrict__ w)
{
    __shared__ float red [2][4];
    __shared__ float red2[2][4];
    int tid  = threadIdx.x;
    int half_ = tid >> 7;
    int t    = tid & 127;
    int wh   = (tid >> 5) & 3;
    size_t row = (size_t)blockIdx.x * 2 + half_;
    uint4* p4 = (uint4*)(w + row * (size_t)L_);   // 2048 halves = 256 uint4

    uint4 ua = p4[t], ub = p4[t + 128];
    float v[16];
    {
        const __half2* ha = (const __half2*)&ua;
        const __half2* hb = (const __half2*)&ub;
        #pragma unroll
        for (int i = 0; i < 4; i++) {
            float2 fa = __half22float2(ha[i]);
            float2 fb = __half22float2(hb[i]);
            v[2 * i + 0] = fa.x; v[2 * i + 1] = fa.y;
            v[8 + 2 * i + 0] = fb.x; v[8 + 2 * i + 1] = fb.y;
        }
    }

    float mx = v[0];
    #pragma unroll
    for (int i = 1; i < 16; i++) mx = fmaxf(mx, v[i]);
    #pragma unroll
    for (int o = 16; o > 0; o >>= 1) mx = fmaxf(mx, __shfl_xor_sync(0xffffffffu, mx, o));
    if ((tid & 31) == 0) red[half_][wh] = mx;
    __syncthreads();
    float m = fmaxf(fmaxf(red[half_][0], red[half_][1]),
                    fmaxf(red[half_][2], red[half_][3]));

    float s = 0.f;
    #pragma unroll
    for (int i = 0; i < 16; i++) { v[i] = __expf(v[i] - m); s += v[i]; }
    #pragma unroll
    for (int o = 16; o > 0; o >>= 1) s += __shfl_xor_sync(0xffffffffu, s, o);
    if ((tid & 31) == 0) red2[half_][wh] = s;
    __syncthreads();
    float inv = 1.f / (red2[half_][0] + red2[half_][1] + red2[half_][2] + red2[half_][3]);

    uint4 oa, ob;
    __half2* qa = (__half2*)&oa;
    __half2* qb = (__half2*)&ob;
    #pragma unroll
    for (int i = 0; i < 4; i++) {
        qa[i] = __floats2half2_rn(v[2 * i + 0] * inv, v[2 * i + 1] * inv);
        qb[i] = __floats2half2_rn(v[8 + 2 * i + 0] * inv, v[8 + 2 * i + 1] * inv);
    }
    p4[t]       = oa;
    p4[t + 128] = ob;
}

// ---------------------------------------------------------------------------
// Host orchestration (graph-capturable: kernel launches only)
// Launch order: conv1 is the 4th launch so the harness profile (-s 5 -c 1
// style skip) lands on a real MMA kernel.
// ---------------------------------------------------------------------------
extern "C" void kernel_launch(void* const* d_in, const int* in_sizes, int n_in,
                              void* d_out, int out_size)
{
    (void)in_sizes; (void)n_in; (void)out_size;

    const float* x   = (const float*)d_in[0];
    const int*   t   = (const int*)  d_in[1];
    const float* z0  = (const float*)d_in[2];
    const float* zt  = (const float*)d_in[3];
    const float* tw1 = (const float*)d_in[4];
    const float* tb1 = (const float*)d_in[5];
    const float* tw2 = (const float*)d_in[6];
    const float* tb2 = (const float*)d_in[7];
    const float* tpw = (const float*)d_in[8];
    const float* tpb = (const float*)d_in[9];
    const float* zpw = (const float*)d_in[10];
    const float* zpb = (const float*)d_in[11];
    const float* n1g = (const float*)d_in[12];
    const float* n1b = (const float*)d_in[13];
    const float* n2g = (const float*)d_in[14];
    const float* n2b = (const float*)d_in[15];
    const float* ng  = (const float*)d_in[16];
    const float* nb  = (const float*)d_in[17];
    const float* c1w = (const float*)d_in[18];
    const float* c1b = (const float*)d_in[19];
    const float* c2w = (const float*)d_in[20];
    const float* c2b = (const float*)d_in[21];
    const float* qw  = (const float*)d_in[22];
    const float* qb  = (const float*)d_in[23];
    const float* kw  = (const float*)d_in[24];
    const float* kb  = (const float*)d_in[25];
    const float* vw  = (const float*)d_in[26];
    const float* vb  = (const float*)d_in[27];
    const float* pw  = (const float*)d_in[28];
    const float* pb  = (const float*)d_in[29];
    float* out = (float*)d_out;

    __half *p_t1, *p_hnT, *p_qk, *p_v, *p_h2T, *p_wS, *p_wrh;
    float *p_h, *p_x1, *p_add, *p_bqk;
    float2* p_st;
    cudaGetSymbolAddress((void**)&p_t1,  g_t1);
    cudaGetSymbolAddress((void**)&p_h,   g_h);
    cudaGetSymbolAddress((void**)&p_x1,  g_x1);
    cudaGetSymbolAddress((void**)&p_hnT, g_hnT);
    cudaGetSymbolAddress((void**)&p_qk,  g_qk);
    cudaGetSymbolAddress((void**)&p_v,   g_v);
    cudaGetSymbolAddress((void**)&p_h2T, g_h2T);
    cudaGetSymbolAddress((void**)&p_wS,  g_wS);
    cudaGetSymbolAddress((void**)&p_add, g_add);
    cudaGetSymbolAddress((void**)&p_wrh, g_wrh);
    cudaGetSymbolAddress((void**)&p_bqk, g_bqk);
    cudaGetSymbolAddress((void**)&p_st,  g_st);

    __half* wr_qk  = p_wrh;                                  // [512][256]
    __half* wr_v   = p_wrh + 512 * C_;                       // [256][256]
    __half* wr_p   = wr_v + C_ * C_;                         // [256][256]
    __half* wr_c1  = wr_p + C_ * C_;                         // [256][768]
    __half* wr_c2  = wr_c1 + C_ * C_ * 3;                    // [256][768]

    // dynamic-smem attributes (host-side, idempotent)
    cudaFuncSetAttribute(gemm_f16<2, false, true>,
                         cudaFuncAttributeMaxDynamicSharedMemorySize, GEMM_SMEM);
    cudaFuncSetAttribute(gemm_f16<1, false, true>,
                         cudaFuncAttributeMaxDynamicSharedMemorySize, GEMM_SMEM);
    cudaFuncSetAttribute(gemm_f16<0, false, true>,
                         cudaFuncAttributeMaxDynamicSharedMemorySize, GEMM_SMEM);
    cudaFuncSetAttribute(gemm_f16<1, true, false>,
                         cudaFuncAttributeMaxDynamicSharedMemorySize, GEMM_SMEM);
    cudaFuncSetAttribute(conv_f16<true, false>,
                         cudaFuncAttributeMaxDynamicSharedMemorySize, CONV_SMEM);
    cudaFuncSetAttribute(conv_f16<false, true>,
                         cudaFuncAttributeMaxDynamicSharedMemorySize, CONV_SMEM);

    const size_t sCL  = (size_t)C_ * L_;    // [B,C,L] / [B,L,C] batch stride
    const size_t sQK  = (size_t)L_ * 512;   // [B,L,512] batch stride
    const size_t sLL  = (size_t)L_ * L_;    // [B,L,L] batch stride

    dim3 gconv(L_ / 128, C_ / 128, B_);

    // (1) conv1 weight prep, (2) temb, (3) norm1, (4) conv1 <- profiled
    round_f16_kernel<<<(C_ * C_ * 3 + 255) / 256, 256>>>(c1w, wr_c1, C_ * C_ * 3);
    temb_kernel<<<B_, 512>>>(t, z0, zt, tw1, tb1, tw2, tb2, tpw, tpb, zpw, zpb);
    norm_kernel<<<B_ * C_, 256>>>(x, p_t1, n1g, n1b);
    conv_f16<true, false><<<gconv, 256, CONV_SMEM>>>(p_t1, wr_c1, c1b,
                                                     p_add, nullptr, p_h);

    // remaining weight prep
    round_f16_kernel<<<(C_ * C_ * 3 + 255) / 256, 256>>>(c2w, wr_c2, C_ * C_ * 3);
    concat_qk<<<(512 * C_ + 255) / 256, 256>>>(qw, kw, qb, kb, wr_qk, p_bqk);
    round_f16_kernel<<<(C_ * C_ + 255) / 256, 256>>>(vw, wr_v, C_ * C_);
    round_f16_kernel<<<(C_ * C_ + 255) / 256, 256>>>(pw, wr_p, C_ * C_);

    // stage 2: t1 = f16(silu(chan_norm(h, n2))); x1 = x + conv2(t1)
    norm_kernel<<<B_ * C_, 256>>>(p_h, p_t1, n2g, n2b);
    conv_f16<false, true><<<gconv, 256, CONV_SMEM>>>(p_t1, wr_c2, c2b,
                                                     nullptr, x, p_x1);

    // stage 3: stats(x1, n) -> fused norm+transpose -> hnT [B][L][C] f16
    stats_kernel<<<B_ * C_, 256>>>(p_x1, ng, nb, p_st);
    dim3 gtr(L_ / 32, C_ / 32, B_);
    transpose_norm<<<gtr, 256>>>(p_x1, p_st, p_hnT);

    // qk [L][512] = hnT @ [qw;kw]^T + b(per-n)    M=L, N=512, K=256
    dim3 gqk(512 / 128, L_ / 128, B_);
    gemm_f16<2, false, true><<<gqk, 256, GEMM_SMEM>>>(
        p_hnT, wr_qk, p_bqk, nullptr, p_qk,
        C_, C_, C_, 512, 1.f, sCL, 0, sQK);
    // v [C][L] = vw @ hn + b(per-m)               M=C, N=L, K=256
    dim3 gv(L_ / 128, C_ / 128, B_);
    gemm_f16<1, false, true><<<gv, 256, GEMM_SMEM>>>(
        wr_v, p_hnT, vb, nullptr, p_v,
        C_, C_, C_, L_, 1.f, 0, sCL, sCL);

    // scores[i][j] = (1/16) q[i]·k[j] -> fp16     M=N=L, K=256 (ld 512)
    dim3 gsc(L_ / 128, L_ / 128, B_);
    gemm_f16<0, false, true><<<gsc, 256, GEMM_SMEM>>>(
        p_qk, p_qk + 256, nullptr, nullptr, p_wS,
        C_, 512, 512, L_, 0.0625f, sQK, sQK, sLL);

    // softmax over j: fp16 in-place
    softmax_kernel<<<B_ * L_ / 2, 256>>>(p_wS);

    // h2T[i][c] = sum_j wS[i][j] v[c][j]          M=L, N=C, K=L
    dim3 gh2(C_ / 128, L_ / 128, B_);
    gemm_f16<0, false, true><<<gh2, 256, GEMM_SMEM>>>(
        p_wS, p_v, nullptr, nullptr, p_h2T,
        L_, L_, L_, C_, 1.f, sLL, sCL, sCL);

    // out[c][l] = pw @ h2 + pb + x1               M=C, N=L, K=256, fp32 out
    dim3 gpr(L_ / 128, C_ / 128, B_);
    gemm_f16<1, true, false><<<gpr, 256, GEMM_SMEM>>>(
        wr_p, p_h2T, pb, p_x1, out,
        C_, C_, C_, L_, 1.f, 0, sCL, sCL);
}

// round 16
// speedup vs baseline: 1.6640x; 1.0596x over previous
#include <cuda_runtime.h>
#include <cuda_fp16.h>
#include <math.h>
#include <stdint.h>

typedef unsigned int u32;

// ---------------------------------------------------------------------------
// Problem constants
// ---------------------------------------------------------------------------
constexpr int B_    = 16;
constexpr int C_    = 256;
constexpr int L_    = 2048;
constexpr int ZD_   = 128;
constexpr int TEMB_ = 512;
constexpr size_t BCL = (size_t)B_ * C_ * L_;
constexpr size_t BLL = (size_t)B_ * L_ * L_;

// ---------------------------------------------------------------------------
// Scratch (device globals; allocation-free per harness rules)
// ---------------------------------------------------------------------------
__device__ __align__(16) __half  g_t1 [BCL];                    // silu(norm(.)) fp16
__device__ __align__(16) float   g_h  [BCL];                    // conv1 output
__device__ __align__(16) float   g_x1 [BCL];                    // x + conv2(...)
__device__ __align__(16) __half  g_hnT[BCL];                    // norm(x1)^T [B][L][C]
__device__ __align__(16) __half  g_qk [(size_t)B_ * L_ * 512];  // q|k fused [B][L][512]
__device__ __align__(16) __half  g_v  [BCL];                    // v [B][C][L]
__device__ __align__(16) __half  g_h2T[BCL];                    // attn out [B][L][C]
__device__ __align__(16) __half  g_wS [BLL];                    // scores/softmax fp16
__device__ __align__(16) float   g_add[B_ * C_];                // temb/z projection
__device__ __align__(16) float2  g_st [B_ * C_];                // norm fold (fA, fB)
// fp16 weights: qk(512x256) | vw | pw | c1w | c2w
__device__ __align__(16) __half g_wrh[512 * C_ + 2 * C_ * C_ + 2 * C_ * C_ * 3];
__device__ __align__(16) float  g_bqk[512];                     // qb|kb bias

static __device__ __forceinline__ float silu_f(float x) {
    return x / (1.f + expf(-x));
}

#define MMA_F16(d, a, b)                                                      \
    asm volatile("mma.sync.aligned.m16n8k16.row.col.f32.f16.f16.f32 "         \
                 "{%0,%1,%2,%3},{%4,%5,%6,%7},{%8,%9},{%0,%1,%2,%3};"         \
                 : "+f"(d[0]), "+f"(d[1]), "+f"(d[2]), "+f"(d[3])             \
                 : "r"(a[0]), "r"(a[1]), "r"(a[2]), "r"(a[3]),                \
                   "r"(b[0]), "r"(b[1]))

#define LDSM_X4(r0, r1, r2, r3, addr)                                         \
    asm volatile("ldmatrix.sync.aligned.m8n8.x4.shared.b16 {%0,%1,%2,%3}, [%4];" \
                 : "=r"(r0), "=r"(r1), "=r"(r2), "=r"(r3) : "r"(addr))

#define CP_ASYNC16(dst_u32, src_ptr)                                          \
    asm volatile("cp.async.cg.shared.global [%0], [%1], 16;"                  \
                 :: "r"(dst_u32), "l"(src_ptr))
#define CP_COMMIT()  asm volatile("cp.async.commit_group;")
#define CP_WAIT0()   asm volatile("cp.async.wait_group 0;")
#define CP_WAIT1()   asm volatile("cp.async.wait_group 1;")

static __device__ __forceinline__ u32 smem_u32(const void* p) {
    return (u32)__cvta_generic_to_shared(p);
}

// ---------------------------------------------------------------------------
// Weight prep kernels (tiny, run once per launch)
// ---------------------------------------------------------------------------
__global__ void round_f16_kernel(const float* __restrict__ in,
                                 __half* __restrict__ out, int n)
{
    int i = blockIdx.x * 256 + threadIdx.x;
    if (i < n) out[i] = __float2half_rn(in[i]);
}

// concat qw|kw rows (512x256) + qb|kb (512), fp16 weights, fp32 bias
__global__ void concat_qk(const float* __restrict__ qw,
                          const float* __restrict__ kw,
                          const float* __restrict__ qb,
                          const float* __restrict__ kb,
                          __half* __restrict__ wdst,
                          float* __restrict__ bdst)
{
    int i = blockIdx.x * 256 + threadIdx.x;
    int total = 512 * C_;
    if (i < total) {
        int n = i >> 8;   // /256
        wdst[i] = __float2half_rn(n < C_ ? qw[i] : kw[i - C_ * C_]);
    }
    if (i < 512) bdst[i] = (i < C_) ? qb[i] : kb[i - C_];
}

// ---------------------------------------------------------------------------
// Kernel: timestep embedding MLP + fused add-vector (fp32, tiny)
// ---------------------------------------------------------------------------
__global__ void temb_kernel(const int* __restrict__ t,
                            const float* __restrict__ z0,
                            const float* __restrict__ zt,
                            const float* __restrict__ tw1, const float* __restrict__ tb1,
                            const float* __restrict__ tw2, const float* __restrict__ tb2,
                            const float* __restrict__ tpw, const float* __restrict__ tpb,
                            const float* __restrict__ zpw, const float* __restrict__ zpb)
{
    __shared__ float se[128];
    __shared__ float s1[512];
    __shared__ float s2[512];
    __shared__ float sz[256];

    int b = blockIdx.x, tid = threadIdx.x;

    if (tid < 64) {
        float f = expf((float)tid * (-logf(10000.f) / 63.f));
        float a = (float)t[b] * f;
        se[tid]      = sinf(a);
        se[64 + tid] = cosf(a);
    }
    if (tid < 128) {
        sz[tid]       = silu_f(z0[b * ZD_ + tid]);
        sz[128 + tid] = silu_f(zt[b * ZD_ + tid]);
    }
    __syncthreads();

    {
        float acc = tb1[tid];
        #pragma unroll 8
        for (int i = 0; i < 128; i++) acc += se[i] * tw1[i * TEMB_ + tid];
        s1[tid] = silu_f(acc);
    }
    __syncthreads();
    {
        float acc = tb2[tid];
        #pragma unroll 8
        for (int k = 0; k < 512; k++) acc += s1[k] * tw2[k * TEMB_ + tid];
        s2[tid] = silu_f(acc);
    }
    __syncthreads();

    if (tid < C_) {
        float acc = tpb[tid] + 2.f * zpb[tid];
        #pragma unroll 8
        for (int j = 0; j < 512; j++) acc += s2[j] * tpw[j * C_ + tid];
        #pragma unroll 8
        for (int i = 0; i < 128; i++) acc += (sz[i] + sz[128 + i]) * zpw[i * C_ + tid];
        g_add[b * C_ + tid] = acc;
    }
}

// ---------------------------------------------------------------------------
// Kernel: per-(b,c) channel norm over L, fused silu, fp16 output (conv input).
// ---------------------------------------------------------------------------
__global__ __launch_bounds__(256) void norm_kernel(const float* __restrict__ in,
                                                   __half* __restrict__ out,
                                                   const float* __restrict__ gam,
                                                   const float* __restrict__ bet)
{
    __shared__ float red[64];
    int row = blockIdx.x, tid = threadIdx.x;
    const float4* p4 = (const float4*)(in + (size_t)row * L_);

    float4 a = p4[tid];
    float4 b = p4[tid + 256];
    float v[8] = { a.x, a.y, a.z, a.w, b.x, b.y, b.z, b.w };
    float s = 0.f, sq = 0.f;
    #pragma unroll
    for (int i = 0; i < 8; i++) { s += v[i]; sq += v[i] * v[i]; }

    #pragma unroll
    for (int o = 16; o > 0; o >>= 1) {
        s  += __shfl_down_sync(0xffffffffu, s,  o);
        sq += __shfl_down_sync(0xffffffffu, sq, o);
    }
    if ((tid & 31) == 0) { red[tid >> 5] = s; red[8 + (tid >> 5)] = sq; }
    __syncthreads();
    if (tid < 32) {
        float aa = (tid < 8) ? red[tid]     : 0.f;
        float b2 = (tid < 8) ? red[8 + tid] : 0.f;
        #pragma unroll
        for (int o = 4; o > 0; o >>= 1) {
            aa += __shfl_down_sync(0xffffffffu, aa, o);
            b2 += __shfl_down_sync(0xffffffffu, b2, o);
        }
        if (tid == 0) { red[32] = aa; red[33] = b2; }
    }
    __syncthreads();

    float mean = red[32] * (1.f / L_);
    float var  = red[33] * (1.f / L_) - mean * mean;
    float rstd = rsqrtf(var + 1e-6f);
    int c = row & (C_ - 1);
    float gm = gam[c], bt = bet[c];

    float o8[8];
    #pragma unroll
    for (int i = 0; i < 8; i++) {
        float y = (v[i] - mean) * rstd * gm + bt;
        o8[i] = y / (1.f + expf(-y));
    }
    __half2* q2 = (__half2*)(out + (size_t)row * L_);
    q2[2 * tid + 0]       = __floats2half2_rn(o8[0], o8[1]);
    q2[2 * tid + 1]       = __floats2half2_rn(o8[2], o8[3]);
    q2[512 + 2 * tid + 0] = __floats2half2_rn(o8[4], o8[5]);
    q2[512 + 2 * tid + 1] = __floats2half2_rn(o8[6], o8[7]);
}

// ---------------------------------------------------------------------------
// Kernel: per-(b,c) norm statistics -> fold factors (fA, fB) for stage 3.
// ---------------------------------------------------------------------------
__global__ __launch_bounds__(256) void stats_kernel(const float* __restrict__ in,
                                                    const float* __restrict__ gam,
                                                    const float* __restrict__ bet,
                                                    float2* __restrict__ st)
{
    __shared__ float red[64];
    int row = blockIdx.x, tid = threadIdx.x;
    const float4* p4 = (const float4*)(in + (size_t)row * L_);

    float4 a = p4[tid];
    float4 b = p4[tid + 256];
    float s  = a.x + a.y + a.z + a.w + b.x + b.y + b.z + b.w;
    float sq = a.x * a.x + a.y * a.y + a.z * a.z + a.w * a.w
             + b.x * b.x + b.y * b.y + b.z * b.z + b.w * b.w;

    #pragma unroll
    for (int o = 16; o > 0; o >>= 1) {
        s  += __shfl_down_sync(0xffffffffu, s,  o);
        sq += __shfl_down_sync(0xffffffffu, sq, o);
    }
    if ((tid & 31) == 0) { red[tid >> 5] = s; red[8 + (tid >> 5)] = sq; }
    __syncthreads();
    if (tid == 0) {
        float S = 0.f, SQ = 0.f;
        #pragma unroll
        for (int i = 0; i < 8; i++) { S += red[i]; SQ += red[8 + i]; }
        float mean = S * (1.f / L_);
        float var  = SQ * (1.f / L_) - mean * mean;
        float rstd = rsqrtf(var + 1e-6f);
        int c = row & (C_ - 1);
        float fA = rstd * gam[c];
        st[row] = make_float2(fA, bet[c] - mean * fA);
    }
}

// ---------------------------------------------------------------------------
// Kernel: fused norm + 32x32 transpose, fp32 [B][C][L] -> fp16 [B][L][C].
// ---------------------------------------------------------------------------
__global__ __launch_bounds__(256) void transpose_norm(const float* __restrict__ in,
                                                      const float2* __restrict__ st,
                                                      __half* __restrict__ out)
{
    __shared__ float tile[32][33];
    int b = blockIdx.z;
    int l0 = blockIdx.x * 32, c0 = blockIdx.y * 32;
    int tx = threadIdx.x & 31, ty = threadIdx.x >> 5;
    #pragma unroll
    for (int i = 0; i < 4; i++) {
        int c = c0 + ty + i * 8;
        float2 f = st[b * C_ + c];
        float x = in[((size_t)(b * C_ + c)) * L_ + l0 + tx];
        tile[ty + i * 8][tx] = fmaf(x, f.x, f.y);
    }
    __syncthreads();
    #pragma unroll
    for (int i = 0; i < 4; i++) {
        int l = l0 + ty + i * 8;
        out[((size_t)b * L_ + l) * C_ + c0 + tx] = __float2half_rn(tile[tx][ty + i * 8]);
    }
}

// ---------------------------------------------------------------------------
// fp16 tensor-core GEMM (m16n8k16), cp.async 2-stage pipeline, k-tile 64,
// FORCED 2 CTAs/SM. Fragment loads via ldmatrix.x4 (bit-identical fragments).
// ---------------------------------------------------------------------------
constexpr int GEMM_SMEM = 2 * 2 * 128 * 72 * 2;   // 73728 B; x2 CTAs = 147 KB

template <int BIAS_MODE, bool RES, bool OHALF>
__global__ __launch_bounds__(256, 2) void gemm_f16(
    const __half* __restrict__ A, const __half* __restrict__ Bm,
    const float* __restrict__ bias, const float* __restrict__ res,
    void* __restrict__ Cout, int K, int lda, int ldb, int ldc,
    float alpha, size_t strideA, size_t strideB, size_t strideC)
{
    extern __shared__ __half hsm[];
    __half (*sA)[128][72] = (__half(*)[128][72])hsm;                 // [stage]
    __half (*sB)[128][72] = (__half(*)[128][72])(hsm + 2 * 128 * 72);

    int bz = blockIdx.z;
    A  += strideA * bz;
    Bm += strideB * bz;

    int m0 = blockIdx.y * 128, n0 = blockIdx.x * 128;
    int tid = threadIdx.x, lane = tid & 31, w = tid >> 5;
    int wm = (w & 3) * 32, wn = (w >> 2) * 64;
    int g = lane >> 2, tg = lane & 3;

    // ldmatrix lane addressing: lm = matrix index (0..3), lane8 = row in 8x8
    int lane8 = lane & 7, lm = lane >> 3;
    int a_row = (lm & 1) * 8 + lane8;   // A x4: [m-blk 0,1][k-blk 0] then [k-blk 1]
    int a_col = (lm >> 1) * 8;
    int b_row = (lm >> 1) * 8 + lane8;  // B x4: [n-blk][k-blk] pairs
    int b_col = (lm & 1) * 8;

    int crow[4], cseg[4];
    #pragma unroll
    for (int it = 0; it < 4; it++) {
        int idx = tid + it * 256;
        crow[it] = idx >> 3;
        cseg[it] = (idx & 7) * 8;
    }

    float acc[2][8][4] = {};
    int KT = K / 64;

    auto issue = [&](int kt, int stg) {
        int kk = kt * 64;
        #pragma unroll
        for (int it = 0; it < 4; it++) {
            CP_ASYNC16(smem_u32(&sA[stg][crow[it]][cseg[it]]),
                       &A[(size_t)(m0 + crow[it]) * lda + kk + cseg[it]]);
            CP_ASYNC16(smem_u32(&sB[stg][crow[it]][cseg[it]]),
                       &Bm[(size_t)(n0 + crow[it]) * ldb + kk + cseg[it]]);
        }
    };

    issue(0, 0); CP_COMMIT();

    for (int kt = 0; kt < KT; kt++) {
        int st = kt & 1;
        if (kt + 1 < KT) { issue(kt + 1, st ^ 1); CP_COMMIT(); CP_WAIT1(); }
        else             { CP_WAIT0(); }
        __syncthreads();

        #pragma unroll
        for (int ks = 0; ks < 4; ks++) {
            int kb0 = ks * 16;
            u32 afr[2][4], bfr[8][2];
            #pragma unroll
            for (int mt = 0; mt < 2; mt++) {
                LDSM_X4(afr[mt][0], afr[mt][1], afr[mt][2], afr[mt][3],
                        smem_u32(&sA[st][wm + mt * 16 + a_row][kb0 + a_col]));
            }
            #pragma unroll
            for (int p = 0; p < 4; p++) {
                LDSM_X4(bfr[2 * p][0], bfr[2 * p][1], bfr[2 * p + 1][0], bfr[2 * p + 1][1],
                        smem_u32(&sB[st][wn + p * 16 + b_row][kb0 + b_col]));
            }
            #pragma unroll
            for (int mt = 0; mt < 2; mt++)
                #pragma unroll
                for (int nt = 0; nt < 8; nt++)
                    MMA_F16(acc[mt][nt], afr[mt], bfr[nt]);
        }
        __syncthreads();
    }

    // epilogue
    #pragma unroll
    for (int mt = 0; mt < 2; mt++) {
        #pragma unroll
        for (int half = 0; half < 2; half++) {
            int m = m0 + wm + mt * 16 + g + half * 8;
            float bm = (BIAS_MODE == 1) ? bias[m] : 0.f;
            #pragma unroll
            for (int nt = 0; nt < 8; nt++) {
                int n = n0 + wn + nt * 8 + tg * 2;
                float v0 = acc[mt][nt][half * 2 + 0] * alpha;
                float v1 = acc[mt][nt][half * 2 + 1] * alpha;
                if (BIAS_MODE == 1) { v0 += bm; v1 += bm; }
                if (BIAS_MODE == 2) { v0 += bias[n]; v1 += bias[n + 1]; }
                size_t off = strideC * bz + (size_t)m * ldc + n;
                if (RES) {
                    float2 r2 = *(const float2*)&res[off];
                    v0 += r2.x; v1 += r2.y;
                }
                if (OHALF) {
                    *(__half2*)((__half*)Cout + off) = __floats2half2_rn(v0, v1);
                } else {
                    *(float2*)((float*)Cout + off) = make_float2(v0, v1);
                }
            }
        }
    }
}

// ---------------------------------------------------------------------------
// fp16 tensor-core 3-tap conv (implicit GEMM), cp.async 2-stage pipelined.
// k-chunk 96 (32 ci x 3 taps), 8 chunks; ldmatrix fragment loads.
// smem: 2*128*104 (W) + 2*32*144 (raw) + 128*104 (patch) halves = 96 KB.
// ---------------------------------------------------------------------------
constexpr int CONV_SMEM = (2 * 128 * 104 + 2 * 32 * 144 + 128 * 104) * 2;

template <bool ADDV, bool RES>
__global__ __launch_bounds__(256, 2) void conv_f16(
    const __half* __restrict__ in,   // [B][C][L] fp16
    const __half* __restrict__ w,    // [C][768]  fp16
    const float* __restrict__ bias,
    const float* __restrict__ addv,
    const float* __restrict__ resid,
    float* __restrict__ out)
{
    extern __shared__ __half hsmc[];
    __half (*sW)[128][104] = (__half(*)[128][104])hsmc;              // [stage]
    __half (*sR)[32][144]  = (__half(*)[32][144])(hsmc + 2 * 128 * 104);
    __half (*sP)[104]      = (__half(*)[104])(hsmc + 2 * 128 * 104 + 2 * 32 * 144);

    int b  = blockIdx.z;
    int m0 = blockIdx.y * 128;
    int l0 = blockIdx.x * 128;
    int tid = threadIdx.x, lane = tid & 31, wid = tid >> 5;
    int wm = (wid & 3) * 32, wn = (wid >> 2) * 64;
    int g = lane >> 2, tg = lane & 3;

    int lane8 = lane & 7, lm = lane >> 3;
    int a_row = (lm & 1) * 8 + lane8;
    int a_col = (lm >> 1) * 8;
    int b_row = (lm >> 1) * 8 + lane8;
    int b_col = (lm & 1) * 8;

    auto issue_stage = [&](int kt, int stg) {
        int k0 = kt * 96, ci0 = kt * 32;
        #pragma unroll
        for (int it = 0; it < 6; it++) {
            int idx = tid + it * 256;
            int row = idx / 12, seg = (idx % 12) * 8;
            CP_ASYNC16(smem_u32(&sW[stg][row][seg]),
                       &w[(size_t)(m0 + row) * 768 + k0 + seg]);
        }
        for (int idx = tid; idx < 32 * 18; idx += 256) {
            int c = idx / 18, ch = (idx % 18) * 8;
            int l = l0 - 8 + ch;
            if (l >= 0 && l + 7 < L_) {
                CP_ASYNC16(smem_u32(&sR[stg][c][ch]),
                           &in[((size_t)(b * C_ + ci0 + c)) * L_ + l]);
            } else {
                *(uint4*)&sR[stg][c][ch] = make_uint4(0u, 0u, 0u, 0u);
            }
        }
    };

    float acc[2][8][4] = {};

    issue_stage(0, 0);
    CP_COMMIT();

    for (int kt = 0; kt < 8; kt++) {
        int st = kt & 1;
        CP_WAIT0();
        __syncthreads();

        // build patch [l][3*ci+t] from raw fp16 rows (LDS)
        for (int idx = tid; idx < 32 * 132; idx += 256) {
            int c = idx / 132, p = idx % 132;
            if (p < 130) {
                __half v = sR[st][c][p + 7];   // raw idx 7 <=> l = l0-1
                #pragma unroll
                for (int t_ = 0; t_ < 3; t_++) {
                    int j = p - t_;
                    if (j >= 0 && j < 128) sP[j][3 * c + t_] = v;
                }
            }
        }
        if (kt + 1 < 8) { issue_stage(kt + 1, st ^ 1); CP_COMMIT(); }
        __syncthreads();

        #pragma unroll
        for (int ks = 0; ks < 6; ks++) {
            int kb0 = ks * 16;
            u32 afr[2][4], bfr[8][2];
            #pragma unroll
            for (int mt = 0; mt < 2; mt++) {
                LDSM_X4(afr[mt][0], afr[mt][1], afr[mt][2], afr[mt][3],
                        smem_u32(&sW[st][wm + mt * 16 + a_row][kb0 + a_col]));
            }
            #pragma unroll
            for (int p = 0; p < 4; p++) {
                LDSM_X4(bfr[2 * p][0], bfr[2 * p][1], bfr[2 * p + 1][0], bfr[2 * p + 1][1],
                        smem_u32(&sP[wn + p * 16 + b_row][kb0 + b_col]));
            }
            #pragma unroll
            for (int mt = 0; mt < 2; mt++)
                #pragma unroll
                for (int nt = 0; nt < 8; nt++)
                    MMA_F16(acc[mt][nt], afr[mt], bfr[nt]);
        }
    }

    #pragma unroll
    for (int mt = 0; mt < 2; mt++) {
        #pragma unroll
        for (int half = 0; half < 2; half++) {
            int m = m0 + wm + mt * 16 + g + half * 8;
            float base = bias[m];
            if (ADDV) base += addv[b * C_ + m];
            #pragma unroll
            for (int nt = 0; nt < 8; nt++) {
                int n = l0 + wn + nt * 8 + tg * 2;
                float v0 = acc[mt][nt][half * 2 + 0] + base;
                float v1 = acc[mt][nt][half * 2 + 1] + base;
                size_t off = ((size_t)(b * C_ + m)) * L_ + n;
                if (RES) {
                    float2 r2 = *(const float2*)&resid[off];
                    v0 += r2.x; v1 += r2.y;
                }
                *(float2*)&out[off] = make_float2(v0, v1);
            }
        }
    }
}

// ---------------------------------------------------------------------------
// Row softmax — fp16 in-place. 2 rows per block, 128 thr/row.
// ---------------------------------------------------------------------------
__global__ __launch_bounds__(256) void softmax_kernel(__half* __restrict__ w)
{
    __shared__ float red [2][4];
    __shared__ float red2[2][4];
    int tid  = threadIdx.x;
    int half_ = tid >> 7;
    int t    = tid & 127;
    int wh   = (tid >> 5) & 3;
    size_t row = (size_t)blockIdx.x * 2 + half_;
    uint4* p4 = (uint4*)(w + row * (size_t)L_);   // 2048 halves = 256 uint4

    uint4 ua = p4[t], ub = p4[t + 128];
    float v[16];
    {
        const __half2* ha = (const __half2*)&ua;
        const __half2* hb = (const __half2*)&ub;
        #pragma unroll
        for (int i = 0; i < 4; i++) {
            float2 fa = __half22float2(ha[i]);
            float2 fb = __half22float2(hb[i]);
            v[2 * i + 0] = fa.x; v[2 * i + 1] = fa.y;
            v[8 + 2 * i + 0] = fb.x; v[8 + 2 * i + 1] = fb.y;
        }
    }

    float mx = v[0];
    #pragma unroll
    for (int i = 1; i < 16; i++) mx = fmaxf(mx, v[i]);
    #pragma unroll
    for (int o = 16; o > 0; o >>= 1) mx = fmaxf(mx, __shfl_xor_sync(0xffffffffu, mx, o));
    if ((tid & 31) == 0) red[half_][wh] = mx;
    __syncthreads();
    float m = fmaxf(fmaxf(red[half_][0], red[half_][1]),
                    fmaxf(red[half_][2], red[half_][3]));

    float s = 0.f;
    #pragma unroll
    for (int i = 0; i < 16; i++) { v[i] = __expf(v[i] - m); s += v[i]; }
    #pragma unroll
    for (int o = 16; o > 0; o >>= 1) s += __shfl_xor_sync(0xffffffffu, s, o);
    if ((tid & 31) == 0) red2[half_][wh] = s;
    __syncthreads();
    float inv = 1.f / (red2[half_][0] + red2[half_][1] + red2[half_][2] + red2[half_][3]);

    uint4 oa, ob;
    __half2* qa = (__half2*)&oa;
    __half2* qb = (__half2*)&ob;
    #pragma unroll
    for (int i = 0; i < 4; i++) {
        qa[i] = __floats2half2_rn(v[2 * i + 0] * inv, v[2 * i + 1] * inv);
        qb[i] = __floats2half2_rn(v[8 + 2 * i + 0] * inv, v[8 + 2 * i + 1] * inv);
    }
    p4[t]       = oa;
    p4[t + 128] = ob;
}

// ---------------------------------------------------------------------------
// Host orchestration (graph-capturable: kernel launches only)
// ---------------------------------------------------------------------------
extern "C" void kernel_launch(void* const* d_in, const int* in_sizes, int n_in,
                              void* d_out, int out_size)
{
    (void)in_sizes; (void)n_in; (void)out_size;

    const float* x   = (const float*)d_in[0];
    const int*   t   = (const int*)  d_in[1];
    const float* z0  = (const float*)d_in[2];
    const float* zt  = (const float*)d_in[3];
    const float* tw1 = (const float*)d_in[4];
    const float* tb1 = (const float*)d_in[5];
    const float* tw2 = (const float*)d_in[6];
    const float* tb2 = (const float*)d_in[7];
    const float* tpw = (const float*)d_in[8];
    const float* tpb = (const float*)d_in[9];
    const float* zpw = (const float*)d_in[10];
    const float* zpb = (const float*)d_in[11];
    const float* n1g = (const float*)d_in[12];
    const float* n1b = (const float*)d_in[13];
    const float* n2g = (const float*)d_in[14];
    const float* n2b = (const float*)d_in[15];
    const float* ng  = (const float*)d_in[16];
    const float* nb  = (const float*)d_in[17];
    const float* c1w = (const float*)d_in[18];
    const float* c1b = (const float*)d_in[19];
    const float* c2w = (const float*)d_in[20];
    const float* c2b = (const float*)d_in[21];
    const float* qw  = (const float*)d_in[22];
    const float* qb  = (const float*)d_in[23];
    const float* kw  = (const float*)d_in[24];
    const float* kb  = (const float*)d_in[25];
    const float* vw  = (const float*)d_in[26];
    const float* vb  = (const float*)d_in[27];
    const float* pw  = (const float*)d_in[28];
    const float* pb  = (const float*)d_in[29];
    float* out = (float*)d_out;

    __half *p_t1, *p_hnT, *p_qk, *p_v, *p_h2T, *p_wS, *p_wrh;
    float *p_h, *p_x1, *p_add, *p_bqk;
    float2* p_st;
    cudaGetSymbolAddress((void**)&p_t1,  g_t1);
    cudaGetSymbolAddress((void**)&p_h,   g_h);
    cudaGetSymbolAddress((void**)&p_x1,  g_x1);
    cudaGetSymbolAddress((void**)&p_hnT, g_hnT);
    cudaGetSymbolAddress((void**)&p_qk,  g_qk);
    cudaGetSymbolAddress((void**)&p_v,   g_v);
    cudaGetSymbolAddress((void**)&p_h2T, g_h2T);
    cudaGetSymbolAddress((void**)&p_wS,  g_wS);
    cudaGetSymbolAddress((void**)&p_add, g_add);
    cudaGetSymbolAddress((void**)&p_wrh, g_wrh);
    cudaGetSymbolAddress((void**)&p_bqk, g_bqk);
    cudaGetSymbolAddress((void**)&p_st,  g_st);

    __half* wr_qk  = p_wrh;                                  // [512][256]
    __half* wr_v   = p_wrh + 512 * C_;                       // [256][256]
    __half* wr_p   = wr_v + C_ * C_;                         // [256][256]
    __half* wr_c1  = wr_p + C_ * C_;                         // [256][768]
    __half* wr_c2  = wr_c1 + C_ * C_ * 3;                    // [256][768]

    // dynamic-smem attributes (host-side, idempotent)
    cudaFuncSetAttribute(gemm_f16<2, false, true>,
                         cudaFuncAttributeMaxDynamicSharedMemorySize, GEMM_SMEM);
    cudaFuncSetAttribute(gemm_f16<1, false, true>,
                         cudaFuncAttributeMaxDynamicSharedMemorySize, GEMM_SMEM);
    cudaFuncSetAttribute(gemm_f16<0, false, true>,
                         cudaFuncAttributeMaxDynamicSharedMemorySize, GEMM_SMEM);
    cudaFuncSetAttribute(gemm_f16<1, true, false>,
                         cudaFuncAttributeMaxDynamicSharedMemorySize, GEMM_SMEM);
    cudaFuncSetAttribute(conv_f16<true, false>,
                         cudaFuncAttributeMaxDynamicSharedMemorySize, CONV_SMEM);
    cudaFuncSetAttribute(conv_f16<false, true>,
                         cudaFuncAttributeMaxDynamicSharedMemorySize, CONV_SMEM);

    const size_t sCL  = (size_t)C_ * L_;    // [B,C,L] / [B,L,C] batch stride
    const size_t sQK  = (size_t)L_ * 512;   // [B,L,512] batch stride
    const size_t sLL  = (size_t)L_ * L_;    // [B,L,L] batch stride

    dim3 gconv(L_ / 128, C_ / 128, B_);

    // (1) conv1 weight prep, (2) temb, (3) norm1, (4) conv1 <- profiled
    round_f16_kernel<<<(C_ * C_ * 3 + 255) / 256, 256>>>(c1w, wr_c1, C_ * C_ * 3);
    temb_kernel<<<B_, 512>>>(t, z0, zt, tw1, tb1, tw2, tb2, tpw, tpb, zpw, zpb);
    norm_kernel<<<B_ * C_, 256>>>(x, p_t1, n1g, n1b);
    conv_f16<true, false><<<gconv, 256, CONV_SMEM>>>(p_t1, wr_c1, c1b,
                                                     p_add, nullptr, p_h);

    // remaining weight prep
    round_f16_kernel<<<(C_ * C_ * 3 + 255) / 256, 256>>>(c2w, wr_c2, C_ * C_ * 3);
    concat_qk<<<(512 * C_ + 255) / 256, 256>>>(qw, kw, qb, kb, wr_qk, p_bqk);
    round_f16_kernel<<<(C_ * C_ + 255) / 256, 256>>>(vw, wr_v, C_ * C_);
    round_f16_kernel<<<(C_ * C_ + 255) / 256, 256>>>(pw, wr_p, C_ * C_);

    // stage 2: t1 = f16(silu(chan_norm(h, n2))); x1 = x + conv2(t1)
    norm_kernel<<<B_ * C_, 256>>>(p_h, p_t1, n2g, n2b);
    conv_f16<false, true><<<gconv, 256, CONV_SMEM>>>(p_t1, wr_c2, c2b,
                                                     nullptr, x, p_x1);

    // stage 3: stats(x1, n) -> fused norm+transpose -> hnT [B][L][C] f16
    stats_kernel<<<B_ * C_, 256>>>(p_x1, ng, nb, p_st);
    dim3 gtr(L_ / 32, C_ / 32, B_);
    transpose_norm<<<gtr, 256>>>(p_x1, p_st, p_hnT);

    // qk [L][512] = hnT @ [qw;kw]^T + b(per-n)    M=L, N=512, K=256
    dim3 gqk(512 / 128, L_ / 128, B_);
    gemm_f16<2, false, true><<<gqk, 256, GEMM_SMEM>>>(
        p_hnT, wr_qk, p_bqk, nullptr, p_qk,
        C_, C_, C_, 512, 1.f, sCL, 0, sQK);
    // v [C][L] = vw @ hn + b(per-m)               M=C, N=L, K=256
    dim3 gv(L_ / 128, C_ / 128, B_);
    gemm_f16<1, false, true><<<gv, 256, GEMM_SMEM>>>(
        wr_v, p_hnT, vb, nullptr, p_v,
        C_, C_, C_, L_, 1.f, 0, sCL, sCL);

    // scores[i][j] = (1/16) q[i]·k[j] -> fp16     M=N=L, K=256 (ld 512)
    dim3 gsc(L_ / 128, L_ / 128, B_);
    gemm_f16<0, false, true><<<gsc, 256, GEMM_SMEM>>>(
        p_qk, p_qk + 256, nullptr, nullptr, p_wS,
        C_, 512, 512, L_, 0.0625f, sQK, sQK, sLL);

    // softmax over j: fp16 in-place
    softmax_kernel<<<B_ * L_ / 2, 256>>>(p_wS);

    // h2T[i][c] = sum_j wS[i][j] v[c][j]          M=L, N=C, K=L
    dim3 gh2(C_ / 128, L_ / 128, B_);
    gemm_f16<0, false, true><<<gh2, 256, GEMM_SMEM>>>(
        p_wS, p_v, nullptr, nullptr, p_h2T,
        L_, L_, L_, C_, 1.f, sLL, sCL, sCL);

    // out[c][l] = pw @ h2 + pb + x1               M=C, N=L, K=256, fp32 out
    dim3 gpr(L_ / 128, C_ / 128, B_);
    gemm_f16<1, true, false><<<gpr, 256, GEMM_SMEM>>>(
        wr_p, p_h2T, pb, p_x1, out,
        C_, C_, C_, L_, 1.f, 0, sCL, sCL);
}

// round 17
// speedup vs baseline: 1.7129x; 1.0294x over previous
#include <cuda_runtime.h>
#include <cuda_fp16.h>
#include <math.h>
#include <stdint.h>

typedef unsigned int u32;

// ---------------------------------------------------------------------------
// Problem constants
// ---------------------------------------------------------------------------
constexpr int B_    = 16;
constexpr int C_    = 256;
constexpr int L_    = 2048;
constexpr int ZD_   = 128;
constexpr int TEMB_ = 512;
constexpr size_t BCL = (size_t)B_ * C_ * L_;
constexpr size_t BLL = (size_t)B_ * L_ * L_;

// ---------------------------------------------------------------------------
// Scratch (device globals; allocation-free per harness rules)
// ---------------------------------------------------------------------------
__device__ __align__(16) __half  g_t1T[BCL];                    // silu(norm(.))^T [B][L][C]
__device__ __align__(16) float   g_h  [BCL];                    // conv1 output [B][C][L]
__device__ __align__(16) float   g_x1 [BCL];                    // x + conv2(...)
__device__ __align__(16) __half  g_hnT[BCL];                    // norm(x1)^T [B][L][C]
__device__ __align__(16) __half  g_qk [(size_t)B_ * L_ * 512];  // q|k fused [B][L][512]
__device__ __align__(16) __half  g_v  [BCL];                    // v [B][C][L]
__device__ __align__(16) __half  g_h2T[BCL];                    // attn out [B][L][C]
__device__ __align__(16) __half  g_wS [BLL];                    // scores/softmax fp16
__device__ __align__(16) float   g_add[B_ * C_];                // temb/z projection
__device__ __align__(16) float2  g_st [B_ * C_];                // norm fold (fA, fB)
// fp16 weights: qk(512x256) | vw | pw | c1wT(3x256x256) | c2wT
__device__ __align__(16) __half g_wrh[512 * C_ + 2 * C_ * C_ + 2 * C_ * C_ * 3];
__device__ __align__(16) float  g_bqk[512];                     // qb|kb bias

static __device__ __forceinline__ float silu_f(float x) {
    return x / (1.f + expf(-x));
}

#define MMA_F16(d, a, b)                                                      \
    asm volatile("mma.sync.aligned.m16n8k16.row.col.f32.f16.f16.f32 "         \
                 "{%0,%1,%2,%3},{%4,%5,%6,%7},{%8,%9},{%0,%1,%2,%3};"         \
                 : "+f"(d[0]), "+f"(d[1]), "+f"(d[2]), "+f"(d[3])             \
                 : "r"(a[0]), "r"(a[1]), "r"(a[2]), "r"(a[3]),                \
                   "r"(b[0]), "r"(b[1]))

#define LDSM_X4(r0, r1, r2, r3, addr)                                         \
    asm volatile("ldmatrix.sync.aligned.m8n8.x4.shared.b16 {%0,%1,%2,%3}, [%4];" \
                 : "=r"(r0), "=r"(r1), "=r"(r2), "=r"(r3) : "r"(addr))

#define CP_ASYNC16(dst_u32, src_ptr)                                          \
    asm volatile("cp.async.cg.shared.global [%0], [%1], 16;"                  \
                 :: "r"(dst_u32), "l"(src_ptr))
#define CP_COMMIT()  asm volatile("cp.async.commit_group;")
#define CP_WAIT0()   asm volatile("cp.async.wait_group 0;")
#define CP_WAIT1()   asm volatile("cp.async.wait_group 1;")

static __device__ __forceinline__ u32 smem_u32(const void* p) {
    return (u32)__cvta_generic_to_shared(p);
}

// ---------------------------------------------------------------------------
// mega_prep: one launch does temb-MLP (+add vector) AND all weight preps.
//   blocks [0,16): temb per batch
//   blocks [16,400): c1 wT[t][o][ci] = c1w[o][ci*3+t]   (3*C*C = 196608)
//   blocks [400,784): c2 wT
//   blocks [784,1040): qk concat weights (+ bias in first block)
//   blocks [1040,1168): vw -> fp16
//   blocks [1168,1296): pw -> fp16
// ---------------------------------------------------------------------------
__global__ __launch_bounds__(512) void mega_prep(
    const int* __restrict__ t,
    const float* __restrict__ z0, const float* __restrict__ zt,
    const float* __restrict__ tw1, const float* __restrict__ tb1,
    const float* __restrict__ tw2, const float* __restrict__ tb2,
    const float* __restrict__ tpw, const float* __restrict__ tpb,
    const float* __restrict__ zpw, const float* __restrict__ zpb,
    const float* __restrict__ c1w, const float* __restrict__ c2w,
    const float* __restrict__ qw,  const float* __restrict__ kw,
    const float* __restrict__ qb,  const float* __restrict__ kb,
    const float* __restrict__ vw,  const float* __restrict__ pw,
    __half* __restrict__ wc1T, __half* __restrict__ wc2T,
    __half* __restrict__ wqk,  float* __restrict__ bqk,
    __half* __restrict__ wv,   __half* __restrict__ wp)
{
    __shared__ float se[128];
    __shared__ float s1[512];
    __shared__ float s2[512];
    __shared__ float sz[256];

    int bid = blockIdx.x, tid = threadIdx.x;

    if (bid < 16) {                       // ---- temb path ----
        int b = bid;
        if (tid < 64) {
            float f = expf((float)tid * (-logf(10000.f) / 63.f));
            float a = (float)t[b] * f;
            se[tid]      = sinf(a);
            se[64 + tid] = cosf(a);
        }
        if (tid < 128) {
            sz[tid]       = silu_f(z0[b * ZD_ + tid]);
            sz[128 + tid] = silu_f(zt[b * ZD_ + tid]);
        }
        __syncthreads();
        {
            float acc = tb1[tid];
            #pragma unroll 8
            for (int i = 0; i < 128; i++) acc += se[i] * tw1[i * TEMB_ + tid];
            s1[tid] = silu_f(acc);
        }
        __syncthreads();
        {
            float acc = tb2[tid];
            #pragma unroll 8
            for (int k = 0; k < 512; k++) acc += s1[k] * tw2[k * TEMB_ + tid];
            s2[tid] = silu_f(acc);
        }
        __syncthreads();
        if (tid < C_) {
            float acc = tpb[tid] + 2.f * zpb[tid];
            #pragma unroll 8
            for (int j = 0; j < 512; j++) acc += s2[j] * tpw[j * C_ + tid];
            #pragma unroll 8
            for (int i = 0; i < 128; i++) acc += (sz[i] + sz[128 + i]) * zpw[i * C_ + tid];
            g_add[b * C_ + tid] = acc;
        }
    } else if (bid < 400) {               // ---- c1 wT ----
        int i = (bid - 16) * 512 + tid;
        int t_ = i >> 16, rem = i & 65535;
        int o = rem >> 8, ci = rem & 255;
        wc1T[i] = __float2half_rn(c1w[o * 768 + ci * 3 + t_]);
    } else if (bid < 784) {               // ---- c2 wT ----
        int i = (bid - 400) * 512 + tid;
        int t_ = i >> 16, rem = i & 65535;
        int o = rem >> 8, ci = rem & 255;
        wc2T[i] = __float2half_rn(c2w[o * 768 + ci * 3 + t_]);
    } else if (bid < 1040) {              // ---- qk concat ----
        int i = (bid - 784) * 512 + tid;
        int n = i >> 8;
        wqk[i] = __float2half_rn(n < C_ ? qw[i] : kw[i - C_ * C_]);
        if (bid == 784) bqk[tid] = (tid < C_) ? qb[tid] : kb[tid - C_];
    } else if (bid < 1168) {              // ---- vw ----
        int i = (bid - 1040) * 512 + tid;
        wv[i] = __float2half_rn(vw[i]);
    } else {                              // ---- pw ----
        int i = (bid - 1168) * 512 + tid;
        wp[i] = __float2half_rn(pw[i]);
    }
}

// ---------------------------------------------------------------------------
// Kernel: per-(b,c) norm statistics -> fold factors (fA, fB).
// ---------------------------------------------------------------------------
__global__ __launch_bounds__(256) void stats_kernel(const float* __restrict__ in,
                                                    const float* __restrict__ gam,
                                                    const float* __restrict__ bet,
                                                    float2* __restrict__ st)
{
    __shared__ float red[64];
    int row = blockIdx.x, tid = threadIdx.x;
    const float4* p4 = (const float4*)(in + (size_t)row * L_);

    float4 a = p4[tid];
    float4 b = p4[tid + 256];
    float s  = a.x + a.y + a.z + a.w + b.x + b.y + b.z + b.w;
    float sq = a.x * a.x + a.y * a.y + a.z * a.z + a.w * a.w
             + b.x * b.x + b.y * b.y + b.z * b.z + b.w * b.w;

    #pragma unroll
    for (int o = 16; o > 0; o >>= 1) {
        s  += __shfl_down_sync(0xffffffffu, s,  o);
        sq += __shfl_down_sync(0xffffffffu, sq, o);
    }
    if ((tid & 31) == 0) { red[tid >> 5] = s; red[8 + (tid >> 5)] = sq; }
    __syncthreads();
    if (tid == 0) {
        float S = 0.f, SQ = 0.f;
        #pragma unroll
        for (int i = 0; i < 8; i++) { S += red[i]; SQ += red[8 + i]; }
        float mean = S * (1.f / L_);
        float var  = SQ * (1.f / L_) - mean * mean;
        float rstd = rsqrtf(var + 1e-6f);
        int c = row & (C_ - 1);
        float fA = rstd * gam[c];
        st[row] = make_float2(fA, bet[c] - mean * fA);
    }
}

// ---------------------------------------------------------------------------
// Kernel: fused norm (+optional silu) + 32x32 transpose,
// fp32 [B][C][L] -> fp16 [B][L][C].
// ---------------------------------------------------------------------------
template <bool SILU>
__global__ __launch_bounds__(256) void transpose_act(const float* __restrict__ in,
                                                     const float2* __restrict__ st,
                                                     __half* __restrict__ out)
{
    __shared__ float tile[32][33];
    int b = blockIdx.z;
    int l0 = blockIdx.x * 32, c0 = blockIdx.y * 32;
    int tx = threadIdx.x & 31, ty = threadIdx.x >> 5;
    #pragma unroll
    for (int i = 0; i < 4; i++) {
        int c = c0 + ty + i * 8;
        float2 f = st[b * C_ + c];
        float x = in[((size_t)(b * C_ + c)) * L_ + l0 + tx];
        float y = fmaf(x, f.x, f.y);
        if (SILU) y = y / (1.f + expf(-y));
        tile[ty + i * 8][tx] = y;
    }
    __syncthreads();
    #pragma unroll
    for (int i = 0; i < 4; i++) {
        int l = l0 + ty + i * 8;
        out[((size_t)b * L_ + l) * C_ + c0 + tx] = __float2half_rn(tile[tx][ty + i * 8]);
    }
}

// ---------------------------------------------------------------------------
// fp16 tensor-core GEMM (m16n8k16), cp.async 2-stage pipeline, k-tile 64,
// FORCED 2 CTAs/SM, ldmatrix fragments. (unchanged from R16 WIN)
// ---------------------------------------------------------------------------
constexpr int GEMM_SMEM = 2 * 2 * 128 * 72 * 2;   // 73728 B; x2 CTAs = 147 KB

template <int BIAS_MODE, bool RES, bool OHALF>
__global__ __launch_bounds__(256, 2) void gemm_f16(
    const __half* __restrict__ A, const __half* __restrict__ Bm,
    const float* __restrict__ bias, const float* __restrict__ res,
    void* __restrict__ Cout, int K, int lda, int ldb, int ldc,
    float alpha, size_t strideA, size_t strideB, size_t strideC)
{
    extern __shared__ __half hsm[];
    __half (*sA)[128][72] = (__half(*)[128][72])hsm;                 // [stage]
    __half (*sB)[128][72] = (__half(*)[128][72])(hsm + 2 * 128 * 72);

    int bz = blockIdx.z;
    A  += strideA * bz;
    Bm += strideB * bz;

    int m0 = blockIdx.y * 128, n0 = blockIdx.x * 128;
    int tid = threadIdx.x, lane = tid & 31, w = tid >> 5;
    int wm = (w & 3) * 32, wn = (w >> 2) * 64;
    int g = lane >> 2, tg = lane & 3;

    int lane8 = lane & 7, lm = lane >> 3;
    int a_row = (lm & 1) * 8 + lane8;
    int a_col = (lm >> 1) * 8;
    int b_row = (lm >> 1) * 8 + lane8;
    int b_col = (lm & 1) * 8;

    int crow[4], cseg[4];
    #pragma unroll
    for (int it = 0; it < 4; it++) {
        int idx = tid + it * 256;
        crow[it] = idx >> 3;
        cseg[it] = (idx & 7) * 8;
    }

    float acc[2][8][4] = {};
    int KT = K / 64;

    auto issue = [&](int kt, int stg) {
        int kk = kt * 64;
        #pragma unroll
        for (int it = 0; it < 4; it++) {
            CP_ASYNC16(smem_u32(&sA[stg][crow[it]][cseg[it]]),
                       &A[(size_t)(m0 + crow[it]) * lda + kk + cseg[it]]);
            CP_ASYNC16(smem_u32(&sB[stg][crow[it]][cseg[it]]),
                       &Bm[(size_t)(n0 + crow[it]) * ldb + kk + cseg[it]]);
        }
    };

    issue(0, 0); CP_COMMIT();

    for (int kt = 0; kt < KT; kt++) {
        int st = kt & 1;
        if (kt + 1 < KT) { issue(kt + 1, st ^ 1); CP_COMMIT(); CP_WAIT1(); }
        else             { CP_WAIT0(); }
        __syncthreads();

        #pragma unroll
        for (int ks = 0; ks < 4; ks++) {
            int kb0 = ks * 16;
            u32 afr[2][4], bfr[8][2];
            #pragma unroll
            for (int mt = 0; mt < 2; mt++) {
                LDSM_X4(afr[mt][0], afr[mt][1], afr[mt][2], afr[mt][3],
                        smem_u32(&sA[st][wm + mt * 16 + a_row][kb0 + a_col]));
            }
            #pragma unroll
            for (int p = 0; p < 4; p++) {
                LDSM_X4(bfr[2 * p][0], bfr[2 * p][1], bfr[2 * p + 1][0], bfr[2 * p + 1][1],
                        smem_u32(&sB[st][wn + p * 16 + b_row][kb0 + b_col]));
            }
            #pragma unroll
            for (int mt = 0; mt < 2; mt++)
                #pragma unroll
                for (int nt = 0; nt < 8; nt++)
                    MMA_F16(acc[mt][nt], afr[mt], bfr[nt]);
        }
        __syncthreads();
    }

    #pragma unroll
    for (int mt = 0; mt < 2; mt++) {
        #pragma unroll
        for (int half = 0; half < 2; half++) {
            int m = m0 + wm + mt * 16 + g + half * 8;
            float bm = (BIAS_MODE == 1) ? bias[m] : 0.f;
            #pragma unroll
            for (int nt = 0; nt < 8; nt++) {
                int n = n0 + wn + nt * 8 + tg * 2;
                float v0 = acc[mt][nt][half * 2 + 0] * alpha;
                float v1 = acc[mt][nt][half * 2 + 1] * alpha;
                if (BIAS_MODE == 1) { v0 += bm; v1 += bm; }
                if (BIAS_MODE == 2) { v0 += bias[n]; v1 += bias[n + 1]; }
                size_t off = strideC * bz + (size_t)m * ldc + n;
                if (RES) {
                    float2 r2 = *(const float2*)&res[off];
                    v0 += r2.x; v1 += r2.y;
                }
                if (OHALF) {
                    *(__half2*)((__half*)Cout + off) = __floats2half2_rn(v0, v1);
                } else {
                    *(float2*)((float*)Cout + off) = make_float2(v0, v1);
                }
            }
        }
    }
}

// ---------------------------------------------------------------------------
// fp16 tensor-core 3-tap conv — PATCH-FREE via transposed input [B][L][C].
// k-chunk = 32 ci, 8 chunks; taps handled as 3 accumulation passes whose
// B-fragments come from row-shifted ldmatrix loads (per-lane row address).
// smem/stage: weights [3][128][40] + input tile [144][40]. 2 CTAs/SM forced.
// ---------------------------------------------------------------------------
constexpr int CONV_SMEM = (2 * 3 * 128 * 40 + 2 * 144 * 40) * 2;  // 84480 B

template <bool ADDV, bool RES>
__global__ __launch_bounds__(256, 2) void conv_f16(
    const __half* __restrict__ inT,  // [B][L][C] fp16
    const __half* __restrict__ wT,   // [3][C][C] fp16 (tap-major)
    const float* __restrict__ bias,
    const float* __restrict__ addv,
    const float* __restrict__ resid,
    float* __restrict__ out)         // [B][C][L] fp32
{
    extern __shared__ __half hsmc[];
    __half (*sW)[3][128][40] = (__half(*)[3][128][40])hsmc;          // [stage]
    __half (*sI)[144][40]    = (__half(*)[144][40])(hsmc + 2 * 3 * 128 * 40);

    int b  = blockIdx.z;
    int m0 = blockIdx.y * 128;   // output channel block
    int l0 = blockIdx.x * 128;   // sequence block
    int tid = threadIdx.x, lane = tid & 31, wid = tid >> 5;
    int wm = (wid & 3) * 32, wn = (wid >> 2) * 64;
    int g = lane >> 2, tg = lane & 3;

    int lane8 = lane & 7, lm = lane >> 3;
    int a_row = (lm & 1) * 8 + lane8;
    int a_col = (lm >> 1) * 8;
    int b_row = (lm >> 1) * 8 + lane8;
    int b_col = (lm & 1) * 8;

    auto issue_stage = [&](int kt, int stg) {
        int ci0 = kt * 32;
        // weights: 3 taps x 128 o x 32 ci = 1536 16B-chunks
        #pragma unroll
        for (int it = 0; it < 6; it++) {
            int idx = tid + it * 256;
            int t_ = idx >> 9;
            int rem = idx & 511;
            int o = rem >> 2, seg = (rem & 2 + (rem & 1)) * 8;  // (rem&3)*8
            seg = (rem & 3) * 8;
            CP_ASYNC16(smem_u32(&sW[stg][t_][o][seg]),
                       &wT[(size_t)(t_ * C_ + m0 + o) * C_ + ci0 + seg]);
        }
        // input tile: rows l0-8 .. l0+135 (144), 32 ci each = 576 chunks
        for (int idx = tid; idx < 576; idx += 256) {
            int row = idx >> 2, seg = (idx & 3) * 8;
            int l = l0 - 8 + row;
            if (l >= 0 && l < L_) {
                CP_ASYNC16(smem_u32(&sI[stg][row][seg]),
                           &inT[((size_t)b * L_ + l) * C_ + ci0 + seg]);
            } else {
                *(uint4*)&sI[stg][row][seg] = make_uint4(0u, 0u, 0u, 0u);
            }
        }
    };

    float acc[2][8][4] = {};

    issue_stage(0, 0);
    CP_COMMIT();

    for (int kt = 0; kt < 8; kt++) {
        int st = kt & 1;
        if (kt + 1 < 8) { issue_stage(kt + 1, st ^ 1); CP_COMMIT(); CP_WAIT1(); }
        else            { CP_WAIT0(); }
        __syncthreads();

        #pragma unroll
        for (int t_ = 0; t_ < 3; t_++) {
            #pragma unroll
            for (int ks = 0; ks < 2; ks++) {
                int kc = ks * 16;
                u32 afr[2][4], bfr[8][2];
                #pragma unroll
                for (int mt = 0; mt < 2; mt++) {
                    LDSM_X4(afr[mt][0], afr[mt][1], afr[mt][2], afr[mt][3],
                            smem_u32(&sW[st][t_][wm + mt * 16 + a_row][kc + a_col]));
                }
                #pragma unroll
                for (int p = 0; p < 4; p++) {
                    LDSM_X4(bfr[2 * p][0], bfr[2 * p][1], bfr[2 * p + 1][0], bfr[2 * p + 1][1],
                            smem_u32(&sI[st][wn + p * 16 + b_row + 7 + t_][kc + b_col]));
                }
                #pragma unroll
                for (int mt = 0; mt < 2; mt++)
                    #pragma unroll
                    for (int nt = 0; nt < 8; nt++)
                        MMA_F16(acc[mt][nt], afr[mt], bfr[nt]);
            }
        }
        __syncthreads();
    }

    #pragma unroll
    for (int mt = 0; mt < 2; mt++) {
        #pragma unroll
        for (int half = 0; half < 2; half++) {
            int m = m0 + wm + mt * 16 + g + half * 8;
            float base = bias[m];
            if (ADDV) base += addv[b * C_ + m];
            #pragma unroll
            for (int nt = 0; nt < 8; nt++) {
                int n = l0 + wn + nt * 8 + tg * 2;
                float v0 = acc[mt][nt][half * 2 + 0] + base;
                float v1 = acc[mt][nt][half * 2 + 1] + base;
                size_t off = ((size_t)(b * C_ + m)) * L_ + n;
                if (RES) {
                    float2 r2 = *(const float2*)&resid[off];
                    v0 += r2.x; v1 += r2.y;
                }
                *(float2*)&out[off] = make_float2(v0, v1);
            }
        }
    }
}

// ---------------------------------------------------------------------------
// Row softmax — fp16 in-place. 2 rows per block, 128 thr/row.
// ---------------------------------------------------------------------------
__global__ __launch_bounds__(256) void softmax_kernel(__half* __restrict__ w)
{
    __shared__ float red [2][4];
    __shared__ float red2[2][4];
    int tid  = threadIdx.x;
    int half_ = tid >> 7;
    int t    = tid & 127;
    int wh   = (tid >> 5) & 3;
    size_t row = (size_t)blockIdx.x * 2 + half_;
    uint4* p4 = (uint4*)(w + row * (size_t)L_);

    uint4 ua = p4[t], ub = p4[t + 128];
    float v[16];
    {
        const __half2* ha = (const __half2*)&ua;
        const __half2* hb = (const __half2*)&ub;
        #pragma unroll
        for (int i = 0; i < 4; i++) {
            float2 fa = __half22float2(ha[i]);
            float2 fb = __half22float2(hb[i]);
            v[2 * i + 0] = fa.x; v[2 * i + 1] = fa.y;
            v[8 + 2 * i + 0] = fb.x; v[8 + 2 * i + 1] = fb.y;
        }
    }

    float mx = v[0];
    #pragma unroll
    for (int i = 1; i < 16; i++) mx = fmaxf(mx, v[i]);
    #pragma unroll
    for (int o = 16; o > 0; o >>= 1) mx = fmaxf(mx, __shfl_xor_sync(0xffffffffu, mx, o));
    if ((tid & 31) == 0) red[half_][wh] = mx;
    __syncthreads();
    float m = fmaxf(fmaxf(red[half_][0], red[half_][1]),
                    fmaxf(red[half_][2], red[half_][3]));

    float s = 0.f;
    #pragma unroll
    for (int i = 0; i < 16; i++) { v[i] = __expf(v[i] - m); s += v[i]; }
    #pragma unroll
    for (int o = 16; o > 0; o >>= 1) s += __shfl_xor_sync(0xffffffffu, s, o);
    if ((tid & 31) == 0) red2[half_][wh] = s;
    __syncthreads();
    float inv = 1.f / (red2[half_][0] + red2[half_][1] + red2[half_][2] + red2[half_][3]);

    uint4 oa, ob;
    __half2* qa = (__half2*)&oa;
    __half2* qb = (__half2*)&ob;
    #pragma unroll
    for (int i = 0; i < 4; i++) {
        qa[i] = __floats2half2_rn(v[2 * i + 0] * inv, v[2 * i + 1] * inv);
        qb[i] = __floats2half2_rn(v[8 + 2 * i + 0] * inv, v[8 + 2 * i + 1] * inv);
    }
    p4[t]       = oa;
    p4[t + 128] = ob;
}

// ---------------------------------------------------------------------------
// Host orchestration (graph-capturable: kernel launches only)
// ---------------------------------------------------------------------------
extern "C" void kernel_launch(void* const* d_in, const int* in_sizes, int n_in,
                              void* d_out, int out_size)
{
    (void)in_sizes; (void)n_in; (void)out_size;

    const float* x   = (const float*)d_in[0];
    const int*   t   = (const int*)  d_in[1];
    const float* z0  = (const float*)d_in[2];
    const float* zt  = (const float*)d_in[3];
    const float* tw1 = (const float*)d_in[4];
    const float* tb1 = (const float*)d_in[5];
    const float* tw2 = (const float*)d_in[6];
    const float* tb2 = (const float*)d_in[7];
    const float* tpw = (const float*)d_in[8];
    const float* tpb = (const float*)d_in[9];
    const float* zpw = (const float*)d_in[10];
    const float* zpb = (const float*)d_in[11];
    const float* n1g = (const float*)d_in[12];
    const float* n1b = (const float*)d_in[13];
    const float* n2g = (const float*)d_in[14];
    const float* n2b = (const float*)d_in[15];
    const float* ng  = (const float*)d_in[16];
    const float* nb  = (const float*)d_in[17];
    const float* c1w = (const float*)d_in[18];
    const float* c1b = (const float*)d_in[19];
    const float* c2w = (const float*)d_in[20];
    const float* c2b = (const float*)d_in[21];
    const float* qw  = (const float*)d_in[22];
    const float* qb  = (const float*)d_in[23];
    const float* kw  = (const float*)d_in[24];
    const float* kb  = (const float*)d_in[25];
    const float* vw  = (const float*)d_in[26];
    const float* vb  = (const float*)d_in[27];
    const float* pw  = (const float*)d_in[28];
    const float* pb  = (const float*)d_in[29];
    float* out = (float*)d_out;

    __half *p_t1T, *p_hnT, *p_qk, *p_v, *p_h2T, *p_wS, *p_wrh;
    float *p_h, *p_x1, *p_add, *p_bqk;
    float2* p_st;
    cudaGetSymbolAddress((void**)&p_t1T, g_t1T);
    cudaGetSymbolAddress((void**)&p_h,   g_h);
    cudaGetSymbolAddress((void**)&p_x1,  g_x1);
    cudaGetSymbolAddress((void**)&p_hnT, g_hnT);
    cudaGetSymbolAddress((void**)&p_qk,  g_qk);
    cudaGetSymbolAddress((void**)&p_v,   g_v);
    cudaGetSymbolAddress((void**)&p_h2T, g_h2T);
    cudaGetSymbolAddress((void**)&p_wS,  g_wS);
    cudaGetSymbolAddress((void**)&p_add, g_add);
    cudaGetSymbolAddress((void**)&p_wrh, g_wrh);
    cudaGetSymbolAddress((void**)&p_bqk, g_bqk);
    cudaGetSymbolAddress((void**)&p_st,  g_st);

    __half* wr_qk  = p_wrh;                                  // [512][256]
    __half* wr_v   = p_wrh + 512 * C_;                       // [256][256]
    __half* wr_p   = wr_v + C_ * C_;                         // [256][256]
    __half* wr_c1T = wr_p + C_ * C_;                         // [3][256][256]
    __half* wr_c2T = wr_c1T + C_ * C_ * 3;                   // [3][256][256]

    // dynamic-smem attributes (host-side, idempotent)
    cudaFuncSetAttribute(gemm_f16<2, false, true>,
                         cudaFuncAttributeMaxDynamicSharedMemorySize, GEMM_SMEM);
    cudaFuncSetAttribute(gemm_f16<1, false, true>,
                         cudaFuncAttributeMaxDynamicSharedMemorySize, GEMM_SMEM);
    cudaFuncSetAttribute(gemm_f16<0, false, true>,
                         cudaFuncAttributeMaxDynamicSharedMemorySize, GEMM_SMEM);
    cudaFuncSetAttribute(gemm_f16<1, true, false>,
                         cudaFuncAttributeMaxDynamicSharedMemorySize, GEMM_SMEM);
    cudaFuncSetAttribute(conv_f16<true, false>,
                         cudaFuncAttributeMaxDynamicSharedMemorySize, CONV_SMEM);
    cudaFuncSetAttribute(conv_f16<false, true>,
                         cudaFuncAttributeMaxDynamicSharedMemorySize, CONV_SMEM);

    const size_t sCL  = (size_t)C_ * L_;    // [B,C,L] / [B,L,C] batch stride
    const size_t sQK  = (size_t)L_ * 512;   // [B,L,512] batch stride
    const size_t sLL  = (size_t)L_ * L_;    // [B,L,L] batch stride

    dim3 gconv(L_ / 128, C_ / 128, B_);
    dim3 gtr(L_ / 32, C_ / 32, B_);

    // (1) mega_prep: temb + all weight conversions in one launch
    mega_prep<<<1296, 512>>>(t, z0, zt, tw1, tb1, tw2, tb2, tpw, tpb, zpw, zpb,
                             c1w, c2w, qw, kw, qb, kb, vw, pw,
                             wr_c1T, wr_c2T, wr_qk, p_bqk, wr_v, wr_p);

    // stage 1: stats(x,n1) -> t1T = f16(silu(norm(x)))^T; h = conv1 + add
    stats_kernel<<<B_ * C_, 256>>>(x, n1g, n1b, p_st);              // (2)
    transpose_act<true><<<gtr, 256>>>(x, p_st, p_t1T);              // (3)
    conv_f16<true, false><<<gconv, 256, CONV_SMEM>>>(               // (4) profiled
        p_t1T, wr_c1T, c1b, p_add, nullptr, p_h);

    // stage 2: stats(h,n2) -> t1T; x1 = x + conv2(t1T)
    stats_kernel<<<B_ * C_, 256>>>(p_h, n2g, n2b, p_st);
    transpose_act<true><<<gtr, 256>>>(p_h, p_st, p_t1T);
    conv_f16<false, true><<<gconv, 256, CONV_SMEM>>>(
        p_t1T, wr_c2T, c2b, nullptr, x, p_x1);

    // stage 3: stats(x1,n) -> hnT = f16(norm(x1))^T
    stats_kernel<<<B_ * C_, 256>>>(p_x1, ng, nb, p_st);
    transpose_act<false><<<gtr, 256>>>(p_x1, p_st, p_hnT);

    // qk [L][512] = hnT @ [qw;kw]^T + b(per-n)    M=L, N=512, K=256
    dim3 gqk(512 / 128, L_ / 128, B_);
    gemm_f16<2, false, true><<<gqk, 256, GEMM_SMEM>>>(
        p_hnT, wr_qk, p_bqk, nullptr, p_qk,
        C_, C_, C_, 512, 1.f, sCL, 0, sQK);
    // v [C][L] = vw @ hn + b(per-m)               M=C, N=L, K=256
    dim3 gv(L_ / 128, C_ / 128, B_);
    gemm_f16<1, false, true><<<gv, 256, GEMM_SMEM>>>(
        wr_v, p_hnT, vb, nullptr, p_v,
        C_, C_, C_, L_, 1.f, 0, sCL, sCL);

    // scores[i][j] = (1/16) q[i]·k[j] -> fp16     M=N=L, K=256 (ld 512)
    dim3 gsc(L_ / 128, L_ / 128, B_);
    gemm_f16<0, false, true><<<gsc, 256, GEMM_SMEM>>>(
        p_qk, p_qk + 256, nullptr, nullptr, p_wS,
        C_, 512, 512, L_, 0.0625f, sQK, sQK, sLL);

    // softmax over j: fp16 in-place
    softmax_kernel<<<B_ * L_ / 2, 256>>>(p_wS);

    // h2T[i][c] = sum_j wS[i][j] v[c][j]          M=L, N=C, K=L
    dim3 gh2(C_ / 128, L_ / 128, B_);
    gemm_f16<0, false, true><<<gh2, 256, GEMM_SMEM>>>(
        p_wS, p_v, nullptr, nullptr, p_h2T,
        L_, L_, L_, C_, 1.f, sLL, sCL, sCL);

    // out[c][l] = pw @ h2 + pb + x1               M=C, N=L, K=256, fp32 out
    dim3 gpr(L_ / 128, C_ / 128, B_);
    gemm_f16<1, true, false><<<gpr, 256, GEMM_SMEM>>>(
        wr_p, p_h2T, pb, p_x1, out,
        C_, C_, C_, L_, 1.f, 0, sCL, sCL);
}